// round 1
// baseline (speedup 1.0000x reference)
#include <cuda_runtime.h>
#include <math.h>

// Problem constants: B=2, S=2048, D=1024, H=16, DH=64
#define M_ROWS 4096          // B*S
#define D_MODEL 1024
#define D_QKV   3072
#define D_FF    4096
#define N_HEADS 16
#define D_HEAD  64

// ------------------- scratch buffers (device globals; no allocation) -------------------
__device__ float g_ln  [M_ROWS * D_MODEL];   // 16 MB (reused for ln1 and ln2 output)
__device__ float g_qkv [M_ROWS * D_QKV];     // 48 MB
__device__ float g_attn[M_ROWS * D_MODEL];   // 16 MB
__device__ float g_x2  [M_ROWS * D_MODEL];   // 16 MB (x + attn_out)
__device__ float g_h1  [M_ROWS * D_FF];      // 64 MB

// ============================ LayerNorm ============================
// one block of 256 threads per row (D=1024, 4 floats/thread)
__global__ __launch_bounds__(256) void ln_kernel(
    const float* __restrict__ x, const float* __restrict__ g,
    const float* __restrict__ b, float* __restrict__ y)
{
    int row = blockIdx.x;
    const float* xr = x + (size_t)row * D_MODEL;
    int tid = threadIdx.x;
    float4 v = *(const float4*)(xr + tid * 4);
    float s = v.x + v.y + v.z + v.w;
    float q = v.x*v.x + v.y*v.y + v.z*v.z + v.w*v.w;
    #pragma unroll
    for (int off = 16; off > 0; off >>= 1) {
        s += __shfl_xor_sync(0xffffffffu, s, off);
        q += __shfl_xor_sync(0xffffffffu, q, off);
    }
    __shared__ float sh_s[8], sh_q[8];
    int w = tid >> 5, lane = tid & 31;
    if (lane == 0) { sh_s[w] = s; sh_q[w] = q; }
    __syncthreads();
    if (tid == 0) {
        float ts = 0.f, tq = 0.f;
        #pragma unroll
        for (int i = 0; i < 8; i++) { ts += sh_s[i]; tq += sh_q[i]; }
        sh_s[0] = ts; sh_q[0] = tq;
    }
    __syncthreads();
    float mean = sh_s[0] * (1.f / D_MODEL);
    float var  = sh_q[0] * (1.f / D_MODEL) - mean * mean;
    float rstd = rsqrtf(var + 1e-5f);
    float4 gv = *(const float4*)(g + tid * 4);
    float4 bv = *(const float4*)(b + tid * 4);
    float4 o;
    o.x = (v.x - mean) * rstd * gv.x + bv.x;
    o.y = (v.y - mean) * rstd * gv.y + bv.y;
    o.z = (v.z - mean) * rstd * gv.z + bv.z;
    o.w = (v.w - mean) * rstd * gv.w + bv.w;
    *(float4*)(y + (size_t)row * D_MODEL + tid * 4) = o;
}

// ============================ SGEMM 128x128x16, 8x8/thread ============================
// C[M,N] = A[M,K] @ B[K,N] (+ bias) (+ gelu | + residual)
// mode: 0 = bias only, 1 = bias + exact GELU, 2 = bias + residual
#define GBM 128
#define GBN 128
#define GBK 16

__device__ __forceinline__ float gelu_exact(float v) {
    return 0.5f * v * (1.0f + erff(v * 0.70710678118654752f));
}

__global__ __launch_bounds__(256) void gemm_kernel(
    const float* __restrict__ A, const float* __restrict__ B,
    const float* __restrict__ bias, const float* __restrict__ res,
    float* __restrict__ C, int M, int N, int K, int mode)
{
    __shared__ float As[GBK][GBM];   // A tile, transposed (k-major)
    __shared__ float Bs[GBK][GBN];

    int tid = threadIdx.x;
    int tx = tid & 15, ty = tid >> 4;
    int row0 = blockIdx.y * GBM;
    int col0 = blockIdx.x * GBN;

    float acc[8][8];
    #pragma unroll
    for (int i = 0; i < 8; i++)
        #pragma unroll
        for (int j = 0; j < 8; j++) acc[i][j] = 0.f;

    const float* Abase = A + (size_t)row0 * K;
    const float* Bbase = B + col0;

    for (int k0 = 0; k0 < K; k0 += GBK) {
        // load A tile (128 x 16), store transposed
        #pragma unroll
        for (int i = 0; i < 2; i++) {
            int idx = tid + i * 256;
            int r = idx >> 2, c = (idx & 3) << 2;
            float4 v = *(const float4*)(Abase + (size_t)r * K + k0 + c);
            As[c + 0][r] = v.x; As[c + 1][r] = v.y;
            As[c + 2][r] = v.z; As[c + 3][r] = v.w;
        }
        // load B tile (16 x 128)
        #pragma unroll
        for (int i = 0; i < 2; i++) {
            int idx = tid + i * 256;
            int kr = idx >> 5, c = (idx & 31) << 2;
            *(float4*)&Bs[kr][c] = *(const float4*)(Bbase + (size_t)(k0 + kr) * N + c);
        }
        __syncthreads();
        #pragma unroll
        for (int k = 0; k < GBK; k++) {
            float a[8], bb[8];
            *(float4*)&a[0]  = *(const float4*)&As[k][ty * 8];
            *(float4*)&a[4]  = *(const float4*)&As[k][ty * 8 + 4];
            *(float4*)&bb[0] = *(const float4*)&Bs[k][tx * 8];
            *(float4*)&bb[4] = *(const float4*)&Bs[k][tx * 8 + 4];
            #pragma unroll
            for (int i = 0; i < 8; i++)
                #pragma unroll
                for (int j = 0; j < 8; j++)
                    acc[i][j] = fmaf(a[i], bb[j], acc[i][j]);
        }
        __syncthreads();
    }

    // epilogue
    #pragma unroll
    for (int i = 0; i < 8; i++) {
        int r = row0 + ty * 8 + i;
        #pragma unroll
        for (int j = 0; j < 8; j += 4) {
            int c = col0 + tx * 8 + j;
            float4 o;
            o.x = acc[i][j + 0] + bias[c + 0];
            o.y = acc[i][j + 1] + bias[c + 1];
            o.z = acc[i][j + 2] + bias[c + 2];
            o.w = acc[i][j + 3] + bias[c + 3];
            if (mode == 1) {
                o.x = gelu_exact(o.x); o.y = gelu_exact(o.y);
                o.z = gelu_exact(o.z); o.w = gelu_exact(o.w);
            } else if (mode == 2) {
                float4 rv = *(const float4*)(res + (size_t)r * N + c);
                o.x += rv.x; o.y += rv.y; o.z += rv.z; o.w += rv.w;
            }
            *(float4*)(C + (size_t)r * N + c) = o;
        }
    }
}

// ============================ Flash attention (fp32) ============================
// BQ = BK = 64, DH = 64. grid = (S/64, B*H), 256 threads (16x16), 4x4 micro-tiles.
// smem (dynamic): qT[64][68] (d-major), kT[64][68] (d-major),
//                 vs[64][68] (t-major), pT[64][68] (p transposed, t-major)
#define AW 68                       // padded width (multiple of 4 for float4 alignment)
#define ATT_SMEM (4 * 64 * AW * 4)  // 69632 bytes

__global__ __launch_bounds__(256) void attn_kernel(
    const float* __restrict__ qkv, float* __restrict__ out)
{
    extern __shared__ float sm[];
    float* qT = sm;
    float* kT = qT + 64 * AW;
    float* vs = kT + 64 * AW;
    float* pT = vs + 64 * AW;

    int tid = threadIdx.x;
    int tx = tid & 15, ty = tid >> 4;
    int bh = blockIdx.y;
    int b = bh >> 4, h = bh & 15;
    int q0 = blockIdx.x * 64;

    const size_t rowstride = D_QKV;
    const float* qbase = qkv + (size_t)b * 2048 * rowstride + h * D_HEAD;
    const float* kbase = qbase + D_MODEL;
    const float* vbase = qbase + 2 * D_MODEL;

    // cooperative tile-load mapping: row lj in tile, 16 d-values starting at ld0
    int lj = tid >> 2;
    int ld0 = (tid & 3) * 16;

    // load Q tile (transposed, d-major)
    {
        const float* src = qbase + (size_t)(q0 + lj) * rowstride + ld0;
        #pragma unroll
        for (int u = 0; u < 16; u += 4) {
            float4 v = *(const float4*)(src + u);
            qT[(ld0 + u + 0) * AW + lj] = v.x;
            qT[(ld0 + u + 1) * AW + lj] = v.y;
            qT[(ld0 + u + 2) * AW + lj] = v.z;
            qT[(ld0 + u + 3) * AW + lj] = v.w;
        }
    }

    float m_i[4], l_i[4], o[4][4];
    #pragma unroll
    for (int i = 0; i < 4; i++) {
        m_i[i] = -1e30f; l_i[i] = 0.f;
        #pragma unroll
        for (int c = 0; c < 4; c++) o[i][c] = 0.f;
    }

    const float scale = 0.125f;  // 1/sqrt(64)

    for (int kt = 0; kt < 2048; kt += 64) {
        __syncthreads();  // previous iteration's P·V done; safe to overwrite kT/vs/pT
        // load K tile (transposed) and V tile (natural)
        {
            const float* ks = kbase + (size_t)(kt + lj) * rowstride + ld0;
            const float* vsrc = vbase + (size_t)(kt + lj) * rowstride + ld0;
            #pragma unroll
            for (int u = 0; u < 16; u += 4) {
                float4 kv4 = *(const float4*)(ks + u);
                kT[(ld0 + u + 0) * AW + lj] = kv4.x;
                kT[(ld0 + u + 1) * AW + lj] = kv4.y;
                kT[(ld0 + u + 2) * AW + lj] = kv4.z;
                kT[(ld0 + u + 3) * AW + lj] = kv4.w;
                *(float4*)(vs + lj * AW + ld0 + u) = *(const float4*)(vsrc + u);
            }
        }
        __syncthreads();

        // S = Q K^T (4x4 per thread)
        float s[4][4];
        #pragma unroll
        for (int i = 0; i < 4; i++)
            #pragma unroll
            for (int j = 0; j < 4; j++) s[i][j] = 0.f;
        #pragma unroll 4
        for (int d = 0; d < 64; d++) {
            float4 qa = *(const float4*)(qT + d * AW + ty * 4);
            float4 kb = *(const float4*)(kT + d * AW + tx * 4);
            float qr[4] = {qa.x, qa.y, qa.z, qa.w};
            float kr[4] = {kb.x, kb.y, kb.z, kb.w};
            #pragma unroll
            for (int i = 0; i < 4; i++)
                #pragma unroll
                for (int j = 0; j < 4; j++)
                    s[i][j] = fmaf(qr[i], kr[j], s[i][j]);
        }

        // online softmax (rows owned by 16 tx-lanes; shfl width 16)
        #pragma unroll
        for (int i = 0; i < 4; i++) {
            #pragma unroll
            for (int j = 0; j < 4; j++) s[i][j] *= scale;
            float rmax = fmaxf(fmaxf(s[i][0], s[i][1]), fmaxf(s[i][2], s[i][3]));
            #pragma unroll
            for (int off = 8; off > 0; off >>= 1)
                rmax = fmaxf(rmax, __shfl_xor_sync(0xffffffffu, rmax, off, 16));
            float mnew = fmaxf(m_i[i], rmax);
            float corr = __expf(m_i[i] - mnew);
            float psum = 0.f;
            #pragma unroll
            for (int j = 0; j < 4; j++) {
                float p = __expf(s[i][j] - mnew);
                s[i][j] = p;
                psum += p;
            }
            #pragma unroll
            for (int off = 8; off > 0; off >>= 1)
                psum += __shfl_xor_sync(0xffffffffu, psum, off, 16);
            l_i[i] = l_i[i] * corr + psum;
            m_i[i] = mnew;
            #pragma unroll
            for (int c = 0; c < 4; c++) o[i][c] *= corr;
        }

        // write P transposed: pT[key][qrow]
        #pragma unroll
        for (int i = 0; i < 4; i++)
            #pragma unroll
            for (int j = 0; j < 4; j++)
                pT[(tx * 4 + j) * AW + ty * 4 + i] = s[i][j];
        __syncthreads();

        // O += P V
        #pragma unroll 4
        for (int t = 0; t < 64; t++) {
            float4 pv = *(const float4*)(pT + t * AW + ty * 4);
            float4 vv = *(const float4*)(vs + t * AW + tx * 4);
            float pr[4] = {pv.x, pv.y, pv.z, pv.w};
            float vr[4] = {vv.x, vv.y, vv.z, vv.w};
            #pragma unroll
            for (int i = 0; i < 4; i++)
                #pragma unroll
                for (int c = 0; c < 4; c++)
                    o[i][c] = fmaf(pr[i], vr[c], o[i][c]);
        }
    }

    // epilogue: divide by l, write to [B,S,D] at column h*64 + d
    #pragma unroll
    for (int i = 0; i < 4; i++) {
        float inv = 1.0f / l_i[i];
        int row = q0 + ty * 4 + i;
        size_t off = ((size_t)b * 2048 + row) * D_MODEL + h * D_HEAD + tx * 4;
        float4 w;
        w.x = o[i][0] * inv; w.y = o[i][1] * inv;
        w.z = o[i][2] * inv; w.w = o[i][3] * inv;
        *(float4*)(out + off) = w;
    }
}

// ============================ launch ============================
extern "C" void kernel_launch(void* const* d_in, const int* in_sizes, int n_in,
                              void* d_out, int out_size)
{
    (void)in_sizes; (void)n_in; (void)out_size;
    const float* x     = (const float*)d_in[0];
    const float* ln1_g = (const float*)d_in[1];
    const float* ln1_b = (const float*)d_in[2];
    const float* w_qkv = (const float*)d_in[3];
    const float* b_qkv = (const float*)d_in[4];
    const float* w_out = (const float*)d_in[5];
    const float* b_out = (const float*)d_in[6];
    const float* ln2_g = (const float*)d_in[7];
    const float* ln2_b = (const float*)d_in[8];
    const float* w1    = (const float*)d_in[9];
    const float* b1    = (const float*)d_in[10];
    const float* w2    = (const float*)d_in[11];
    const float* b2    = (const float*)d_in[12];
    float* out = (float*)d_out;

    float *ln, *qkvb, *attnb, *x2, *h1;
    cudaGetSymbolAddress((void**)&ln,    g_ln);
    cudaGetSymbolAddress((void**)&qkvb,  g_qkv);
    cudaGetSymbolAddress((void**)&attnb, g_attn);
    cudaGetSymbolAddress((void**)&x2,    g_x2);
    cudaGetSymbolAddress((void**)&h1,    g_h1);

    cudaFuncSetAttribute(attn_kernel,
                         cudaFuncAttributeMaxDynamicSharedMemorySize, ATT_SMEM);

    // 1. ln1
    ln_kernel<<<M_ROWS, 256>>>(x, ln1_g, ln1_b, ln);
    // 2. qkv = ln @ w_qkv + b_qkv
    gemm_kernel<<<dim3(D_QKV / GBN, M_ROWS / GBM), 256>>>(
        ln, w_qkv, b_qkv, nullptr, qkvb, M_ROWS, D_QKV, D_MODEL, 0);
    // 3. attention
    attn_kernel<<<dim3(2048 / 64, 2 * N_HEADS), 256, ATT_SMEM>>>(qkvb, attnb);
    // 4. x2 = attn @ w_out + b_out + x
    gemm_kernel<<<dim3(D_MODEL / GBN, M_ROWS / GBM), 256>>>(
        attnb, w_out, b_out, x, x2, M_ROWS, D_MODEL, D_MODEL, 2);
    // 5. ln2
    ln_kernel<<<M_ROWS, 256>>>(x2, ln2_g, ln2_b, ln);
    // 6. h1 = gelu(ln @ w1 + b1)
    gemm_kernel<<<dim3(D_FF / GBN, M_ROWS / GBM), 256>>>(
        ln, w1, b1, nullptr, h1, M_ROWS, D_FF, D_MODEL, 1);
    // 7. out = h1 @ w2 + b2 + x2
    gemm_kernel<<<dim3(D_MODEL / GBN, M_ROWS / GBM), 256>>>(
        h1, w2, b2, x2, out, M_ROWS, D_MODEL, D_FF, 2);
}

// round 5
// speedup vs baseline: 1.6298x; 1.6298x over previous
#include <cuda_runtime.h>
#include <cuda_bf16.h>
#include <math.h>
#include <stdint.h>

// Problem: B=2, S=2048, D=1024, H=16, DH=64
#define M_ROWS 4096
#define D_MODEL 1024
#define D_QKV   3072
#define D_FF    4096
#define N_HEADS 16
#define D_HEAD  64

// ---------------- scratch (device globals; no allocation) ----------------
__device__ float g_qkv[M_ROWS * D_QKV];
__device__ float g_x2 [M_ROWS * D_MODEL];
__device__ unsigned short g_ln_hi[M_ROWS * D_MODEL], g_ln_lo[M_ROWS * D_MODEL];
__device__ unsigned short g_at_hi[M_ROWS * D_MODEL], g_at_lo[M_ROWS * D_MODEL];
__device__ unsigned short g_h1_hi[M_ROWS * D_FF],    g_h1_lo[M_ROWS * D_FF];
// transposed weights [N,K] bf16 hi/lo
__device__ unsigned short g_wqkv_hi[D_QKV * D_MODEL], g_wqkv_lo[D_QKV * D_MODEL];
__device__ unsigned short g_wout_hi[D_MODEL * D_MODEL], g_wout_lo[D_MODEL * D_MODEL];
__device__ unsigned short g_w1_hi[D_FF * D_MODEL],   g_w1_lo[D_FF * D_MODEL];
__device__ unsigned short g_w2_hi[D_MODEL * D_FF],   g_w2_lo[D_MODEL * D_FF];

// ---------------- helpers (baseline sm_80+ features only) ----------------
__device__ __forceinline__ uint32_t smem_u32(const void* p) {
    uint32_t a;
    asm("{ .reg .u64 t; cvta.to.shared.u64 t, %1; cvt.u32.u64 %0, t; }" : "=r"(a) : "l"(p));
    return a;
}
__device__ __forceinline__ void cp16(uint32_t dst, const void* src) {
    asm volatile("cp.async.cg.shared.global [%0], [%1], 16;" :: "r"(dst), "l"(src));
}
#define CP_COMMIT() asm volatile("cp.async.commit_group;" ::: "memory")
#define CP_WAIT1()  asm volatile("cp.async.wait_group 1;" ::: "memory")
#define CP_WAIT0()  asm volatile("cp.async.wait_group 0;" ::: "memory")

#define LDSM_X4(r0, r1, r2, r3, addr) \
    asm volatile("ldmatrix.sync.aligned.m8n8.x4.shared.b16 {%0,%1,%2,%3}, [%4];" \
        : "=r"(r0), "=r"(r1), "=r"(r2), "=r"(r3) : "r"(addr))

#define MMA16816(c, a, b) \
    asm volatile("mma.sync.aligned.m16n8k16.row.col.f32.bf16.bf16.f32 " \
        "{%0,%1,%2,%3}, {%4,%5,%6,%7}, {%8,%9}, {%0,%1,%2,%3};" \
        : "+f"((c)[0]), "+f"((c)[1]), "+f"((c)[2]), "+f"((c)[3]) \
        : "r"((a)[0]), "r"((a)[1]), "r"((a)[2]), "r"((a)[3]), "r"((b)[0]), "r"((b)[1]))

__device__ __forceinline__ float gelu_exact(float v) {
    return 0.5f * v * (1.0f + erff(v * 0.70710678118654752f));
}
__device__ __forceinline__ void split_bf16(float v, unsigned short& hi, unsigned short& lo) {
    __nv_bfloat16 h = __float2bfloat16(v);
    float r = v - __bfloat162float(h);
    hi = __bfloat16_as_ushort(h);
    lo = __bfloat16_as_ushort(__float2bfloat16(r));
}

// ================= weight transpose + bf16 hi/lo split =================
__global__ void wconv_kernel(const float* __restrict__ W,
                             unsigned short* __restrict__ Thi,
                             unsigned short* __restrict__ Tlo, int K, int N)
{
    __shared__ float t[32][33];
    int n0 = blockIdx.x * 32, k0 = blockIdx.y * 32;
    int tx = threadIdx.x, ty = threadIdx.y;
    #pragma unroll
    for (int i = 0; i < 32; i += 8)
        t[ty + i][tx] = W[(size_t)(k0 + ty + i) * N + n0 + tx];
    __syncthreads();
    #pragma unroll
    for (int i = 0; i < 32; i += 8) {
        float v = t[tx][ty + i];
        unsigned short h, l;
        split_bf16(v, h, l);
        size_t o = (size_t)(n0 + ty + i) * K + k0 + tx;
        Thi[o] = h; Tlo[o] = l;
    }
}

// ================= LayerNorm (writes bf16 hi/lo) =================
__global__ __launch_bounds__(256) void ln_kernel(
    const float* __restrict__ x, const float* __restrict__ g,
    const float* __restrict__ b,
    unsigned short* __restrict__ yhi, unsigned short* __restrict__ ylo)
{
    int row = blockIdx.x;
    const float* xr = x + (size_t)row * D_MODEL;
    int tid = threadIdx.x;
    float4 v = *(const float4*)(xr + tid * 4);
    float s = v.x + v.y + v.z + v.w;
    float q = v.x*v.x + v.y*v.y + v.z*v.z + v.w*v.w;
    #pragma unroll
    for (int off = 16; off > 0; off >>= 1) {
        s += __shfl_xor_sync(0xffffffffu, s, off);
        q += __shfl_xor_sync(0xffffffffu, q, off);
    }
    __shared__ float sh_s[8], sh_q[8];
    int w = tid >> 5, lane = tid & 31;
    if (lane == 0) { sh_s[w] = s; sh_q[w] = q; }
    __syncthreads();
    if (tid == 0) {
        float ts = 0.f, tq = 0.f;
        #pragma unroll
        for (int i = 0; i < 8; i++) { ts += sh_s[i]; tq += sh_q[i]; }
        sh_s[0] = ts; sh_q[0] = tq;
    }
    __syncthreads();
    float mean = sh_s[0] * (1.f / D_MODEL);
    float var  = sh_q[0] * (1.f / D_MODEL) - mean * mean;
    float rstd = rsqrtf(var + 1e-5f);
    float4 gv = *(const float4*)(g + tid * 4);
    float4 bv = *(const float4*)(b + tid * 4);
    float o0 = (v.x - mean) * rstd * gv.x + bv.x;
    float o1 = (v.y - mean) * rstd * gv.y + bv.y;
    float o2 = (v.z - mean) * rstd * gv.z + bv.z;
    float o3 = (v.w - mean) * rstd * gv.w + bv.w;
    unsigned short h0,h1,h2,h3,l0,l1,l2,l3;
    split_bf16(o0,h0,l0); split_bf16(o1,h1,l1);
    split_bf16(o2,h2,l2); split_bf16(o3,h3,l3);
    size_t off = (size_t)row * D_MODEL + tid * 4;
    *(uint2*)(yhi + off) = make_uint2((uint32_t)h0 | ((uint32_t)h1 << 16),
                                      (uint32_t)h2 | ((uint32_t)h3 << 16));
    *(uint2*)(ylo + off) = make_uint2((uint32_t)l0 | ((uint32_t)l1 << 16),
                                      (uint32_t)l2 | ((uint32_t)l3 << 16));
}

// ================= HMMA bf16x3 GEMM =================
// C[M,N] = A[M,K] @ W[K,N]; A as hi/lo bf16 [M,K]; W transposed hi/lo bf16 [N,K].
// mode 0: outf = C + bias ; mode 1: (ohi,olo)=split(gelu(C+bias)) ; mode 2: outf = C+bias+res
// BM=BN=128, BK=32. 256 threads = 2x4 warps, warp tile 64x32.
// SMEM per stage: 4 matrices of 128 rows x 80 bytes (32 bf16 + 8B pad). Double buffered.
#define GSTAGE 40960
#define GT_SMEM (2 * GSTAGE)

__global__ __launch_bounds__(256, 1) void gemm_tc(
    const unsigned short* __restrict__ Ahi, const unsigned short* __restrict__ Alo,
    const unsigned short* __restrict__ Bhi, const unsigned short* __restrict__ Blo,
    const float* __restrict__ bias, const float* __restrict__ res,
    float* __restrict__ outf,
    unsigned short* __restrict__ ohi, unsigned short* __restrict__ olo,
    int M, int N, int K, int mode)
{
    extern __shared__ char smem[];
    const uint32_t sb = smem_u32(smem);
    const int tid = threadIdx.x;
    const int wid = tid >> 5, lane = tid & 31;
    const int wr = wid >> 2, wc = wid & 3;     // warp grid 2 (m) x 4 (n)
    const int row0 = blockIdx.y * 128, col0 = blockIdx.x * 128;

    const int lr = tid >> 2;       // 0..63 load row
    const int lj = tid & 3;        // 16B chunk in row

    float c[4][4][4];
    #pragma unroll
    for (int mt = 0; mt < 4; mt++)
        #pragma unroll
        for (int nt = 0; nt < 4; nt++)
            #pragma unroll
            for (int i = 0; i < 4; i++) c[mt][nt][i] = 0.f;

    const int nch = K >> 5;

    // cp.async issue for k-chunk cc into stage s
    auto issue = [&](int cc, int s) {
        const int k0 = cc * 32;
        const uint32_t base = sb + (uint32_t)s * GSTAGE;
        const uint32_t ro = (uint32_t)lr * 80u + (uint32_t)lj * 16u;
        const size_t asrc = (size_t)(row0 + lr) * K + k0 + lj * 8;
        const size_t bsrc = (size_t)(col0 + lr) * K + k0 + lj * 8;
        const size_t step = (size_t)64 * K;
        cp16(base +          ro,            Ahi + asrc);
        cp16(base +          ro + 64 * 80u, Ahi + asrc + step);
        cp16(base + 10240u + ro,            Alo + asrc);
        cp16(base + 10240u + ro + 64 * 80u, Alo + asrc + step);
        cp16(base + 20480u + ro,            Bhi + bsrc);
        cp16(base + 20480u + ro + 64 * 80u, Bhi + bsrc + step);
        cp16(base + 30720u + ro,            Blo + bsrc);
        cp16(base + 30720u + ro + 64 * 80u, Blo + bsrc + step);
    };

    issue(0, 0);
    CP_COMMIT();

    for (int cc = 0; cc < nch; cc++) {
        const int s = cc & 1;
        if (cc + 1 < nch) { issue(cc + 1, s ^ 1); CP_COMMIT(); CP_WAIT1(); }
        else              { CP_WAIT0(); }
        __syncthreads();

        const uint32_t base = sb + (uint32_t)s * GSTAGE;
        const uint32_t aHiB = base;
        const uint32_t aLoB = base + 10240u;
        const uint32_t bHiB = base + 20480u;
        const uint32_t bLoB = base + 30720u;

        #pragma unroll
        for (int kk = 0; kk < 32; kk += 16) {
            uint32_t a[4][4], bh[4][2], bl[4][2];
            const uint32_t acol = (uint32_t)((kk + ((lane >> 4) << 3)) << 1);
            const uint32_t arow = (uint32_t)(wr * 64 + (lane & 15)) * 80u;
            #pragma unroll
            for (int mt = 0; mt < 4; mt++)
                LDSM_X4(a[mt][0], a[mt][1], a[mt][2], a[mt][3],
                        aHiB + arow + (uint32_t)(mt * 16) * 80u + acol);
            {
                const int g = lane >> 3;                 // quad group 0..3
                const int rn = (g >= 2) ? 8 : 0;         // n-offset within 16-row pair
                const uint32_t bcol = (uint32_t)((kk + ((g & 1) << 3)) << 1);
                const uint32_t brow = (uint32_t)(wc * 32 + rn + (lane & 7)) * 80u;
                #pragma unroll
                for (int nt2 = 0; nt2 < 2; nt2++)
                    LDSM_X4(bh[nt2*2][0], bh[nt2*2][1], bh[nt2*2+1][0], bh[nt2*2+1][1],
                            bHiB + brow + (uint32_t)(nt2 * 16) * 80u + bcol);
                #pragma unroll
                for (int nt2 = 0; nt2 < 2; nt2++)
                    LDSM_X4(bl[nt2*2][0], bl[nt2*2][1], bl[nt2*2+1][0], bl[nt2*2+1][1],
                            bLoB + brow + (uint32_t)(nt2 * 16) * 80u + bcol);
            }
            // term 1: Ahi * Bhi
            #pragma unroll
            for (int mt = 0; mt < 4; mt++)
                #pragma unroll
                for (int nt = 0; nt < 4; nt++)
                    MMA16816(c[mt][nt], a[mt], bh[nt]);
            // term 2: Ahi * Blo
            #pragma unroll
            for (int mt = 0; mt < 4; mt++)
                #pragma unroll
                for (int nt = 0; nt < 4; nt++)
                    MMA16816(c[mt][nt], a[mt], bl[nt]);
            // term 3: Alo * Bhi (reload A frags from Alo)
            #pragma unroll
            for (int mt = 0; mt < 4; mt++)
                LDSM_X4(a[mt][0], a[mt][1], a[mt][2], a[mt][3],
                        aLoB + arow + (uint32_t)(mt * 16) * 80u + acol);
            #pragma unroll
            for (int mt = 0; mt < 4; mt++)
                #pragma unroll
                for (int nt = 0; nt < 4; nt++)
                    MMA16816(c[mt][nt], a[mt], bh[nt]);
        }
        __syncthreads();
    }

    // ---------------- epilogue ----------------
    #pragma unroll
    for (int mt = 0; mt < 4; mt++) {
        #pragma unroll
        for (int nt = 0; nt < 4; nt++) {
            const int r = row0 + wr * 64 + mt * 16 + (lane >> 2);
            const int ccol = col0 + wc * 32 + nt * 8 + ((lane & 3) << 1);
            const float b0 = bias[ccol], b1 = bias[ccol + 1];
            #pragma unroll
            for (int hh = 0; hh < 2; hh++) {
                const int rr = r + hh * 8;
                float v0 = c[mt][nt][hh * 2 + 0] + b0;
                float v1 = c[mt][nt][hh * 2 + 1] + b1;
                if (mode == 1) {
                    v0 = gelu_exact(v0); v1 = gelu_exact(v1);
                    unsigned short h0, l0, h1, l1;
                    split_bf16(v0, h0, l0); split_bf16(v1, h1, l1);
                    *(uint32_t*)(ohi + (size_t)rr * N + ccol) = (uint32_t)h0 | ((uint32_t)h1 << 16);
                    *(uint32_t*)(olo + (size_t)rr * N + ccol) = (uint32_t)l0 | ((uint32_t)l1 << 16);
                } else {
                    if (mode == 2) {
                        float2 rv = *(const float2*)(res + (size_t)rr * N + ccol);
                        v0 += rv.x; v1 += rv.y;
                    }
                    *(float2*)(outf + (size_t)rr * N + ccol) = make_float2(v0, v1);
                }
            }
        }
    }
}

// ================= Flash attention (fp32), writes bf16 hi/lo =================
#define AW 68
#define ATT_SMEM (4 * 64 * AW * 4)

__global__ __launch_bounds__(256) void attn_kernel(
    const float* __restrict__ qkv,
    unsigned short* __restrict__ ohi, unsigned short* __restrict__ olo)
{
    extern __shared__ float sm[];
    float* qT = sm;
    float* kT = qT + 64 * AW;
    float* vs = kT + 64 * AW;
    float* pT = vs + 64 * AW;

    int tid = threadIdx.x;
    int tx = tid & 15, ty = tid >> 4;
    int bh = blockIdx.y;
    int b = bh >> 4, h = bh & 15;
    int q0 = blockIdx.x * 64;

    const size_t rowstride = D_QKV;
    const float* qbase = qkv + (size_t)b * 2048 * rowstride + h * D_HEAD;
    const float* kbase = qbase + D_MODEL;
    const float* vbase = qbase + 2 * D_MODEL;

    int lj = tid >> 2;
    int ld0 = (tid & 3) * 16;

    {
        const float* src = qbase + (size_t)(q0 + lj) * rowstride + ld0;
        #pragma unroll
        for (int u = 0; u < 16; u += 4) {
            float4 v = *(const float4*)(src + u);
            qT[(ld0 + u + 0) * AW + lj] = v.x;
            qT[(ld0 + u + 1) * AW + lj] = v.y;
            qT[(ld0 + u + 2) * AW + lj] = v.z;
            qT[(ld0 + u + 3) * AW + lj] = v.w;
        }
    }

    float m_i[4], l_i[4], o[4][4];
    #pragma unroll
    for (int i = 0; i < 4; i++) {
        m_i[i] = -1e30f; l_i[i] = 0.f;
        #pragma unroll
        for (int c = 0; c < 4; c++) o[i][c] = 0.f;
    }
    const float scale = 0.125f;

    for (int kt = 0; kt < 2048; kt += 64) {
        __syncthreads();
        {
            const float* ks = kbase + (size_t)(kt + lj) * rowstride + ld0;
            const float* vsrc = vbase + (size_t)(kt + lj) * rowstride + ld0;
            #pragma unroll
            for (int u = 0; u < 16; u += 4) {
                float4 kv4 = *(const float4*)(ks + u);
                kT[(ld0 + u + 0) * AW + lj] = kv4.x;
                kT[(ld0 + u + 1) * AW + lj] = kv4.y;
                kT[(ld0 + u + 2) * AW + lj] = kv4.z;
                kT[(ld0 + u + 3) * AW + lj] = kv4.w;
                *(float4*)(vs + lj * AW + ld0 + u) = *(const float4*)(vsrc + u);
            }
        }
        __syncthreads();

        float s[4][4];
        #pragma unroll
        for (int i = 0; i < 4; i++)
            #pragma unroll
            for (int j = 0; j < 4; j++) s[i][j] = 0.f;
        #pragma unroll 4
        for (int d = 0; d < 64; d++) {
            float4 qa = *(const float4*)(qT + d * AW + ty * 4);
            float4 kb = *(const float4*)(kT + d * AW + tx * 4);
            float qr[4] = {qa.x, qa.y, qa.z, qa.w};
            float kr[4] = {kb.x, kb.y, kb.z, kb.w};
            #pragma unroll
            for (int i = 0; i < 4; i++)
                #pragma unroll
                for (int j = 0; j < 4; j++)
                    s[i][j] = fmaf(qr[i], kr[j], s[i][j]);
        }

        #pragma unroll
        for (int i = 0; i < 4; i++) {
            #pragma unroll
            for (int j = 0; j < 4; j++) s[i][j] *= scale;
            float rmax = fmaxf(fmaxf(s[i][0], s[i][1]), fmaxf(s[i][2], s[i][3]));
            #pragma unroll
            for (int off = 8; off > 0; off >>= 1)
                rmax = fmaxf(rmax, __shfl_xor_sync(0xffffffffu, rmax, off, 16));
            float mnew = fmaxf(m_i[i], rmax);
            float corr = __expf(m_i[i] - mnew);
            float psum = 0.f;
            #pragma unroll
            for (int j = 0; j < 4; j++) {
                float p = __expf(s[i][j] - mnew);
                s[i][j] = p;
                psum += p;
            }
            #pragma unroll
            for (int off = 8; off > 0; off >>= 1)
                psum += __shfl_xor_sync(0xffffffffu, psum, off, 16);
            l_i[i] = l_i[i] * corr + psum;
            m_i[i] = mnew;
            #pragma unroll
            for (int c = 0; c < 4; c++) o[i][c] *= corr;
        }

        #pragma unroll
        for (int i = 0; i < 4; i++)
            #pragma unroll
            for (int j = 0; j < 4; j++)
                pT[(tx * 4 + j) * AW + ty * 4 + i] = s[i][j];
        __syncthreads();

        #pragma unroll 4
        for (int t = 0; t < 64; t++) {
            float4 pv = *(const float4*)(pT + t * AW + ty * 4);
            float4 vv = *(const float4*)(vs + t * AW + tx * 4);
            float pr[4] = {pv.x, pv.y, pv.z, pv.w};
            float vr[4] = {vv.x, vv.y, vv.z, vv.w};
            #pragma unroll
            for (int i = 0; i < 4; i++)
                #pragma unroll
                for (int c = 0; c < 4; c++)
                    o[i][c] = fmaf(pr[i], vr[c], o[i][c]);
        }
    }

    #pragma unroll
    for (int i = 0; i < 4; i++) {
        float inv = 1.0f / l_i[i];
        int row = q0 + ty * 4 + i;
        size_t off = ((size_t)b * 2048 + row) * D_MODEL + h * D_HEAD + tx * 4;
        float w0 = o[i][0] * inv, w1 = o[i][1] * inv;
        float w2 = o[i][2] * inv, w3 = o[i][3] * inv;
        unsigned short h0,h1,h2,h3,l0,l1,l2,l3;
        split_bf16(w0,h0,l0); split_bf16(w1,h1,l1);
        split_bf16(w2,h2,l2); split_bf16(w3,h3,l3);
        *(uint2*)(ohi + off) = make_uint2((uint32_t)h0 | ((uint32_t)h1 << 16),
                                          (uint32_t)h2 | ((uint32_t)h3 << 16));
        *(uint2*)(olo + off) = make_uint2((uint32_t)l0 | ((uint32_t)l1 << 16),
                                          (uint32_t)l2 | ((uint32_t)l3 << 16));
    }
}

// ================= launch =================
extern "C" void kernel_launch(void* const* d_in, const int* in_sizes, int n_in,
                              void* d_out, int out_size)
{
    (void)in_sizes; (void)n_in; (void)out_size;
    const float* x     = (const float*)d_in[0];
    const float* ln1_g = (const float*)d_in[1];
    const float* ln1_b = (const float*)d_in[2];
    const float* w_qkv = (const float*)d_in[3];
    const float* b_qkv = (const float*)d_in[4];
    const float* w_out = (const float*)d_in[5];
    const float* b_out = (const float*)d_in[6];
    const float* ln2_g = (const float*)d_in[7];
    const float* ln2_b = (const float*)d_in[8];
    const float* w1    = (const float*)d_in[9];
    const float* b1    = (const float*)d_in[10];
    const float* w2    = (const float*)d_in[11];
    const float* b2    = (const float*)d_in[12];
    float* out = (float*)d_out;

    float *qkv, *x2;
    unsigned short *lnh, *lnl, *ath, *atl, *h1h, *h1l;
    unsigned short *wqh, *wql, *woh, *wol, *w1h, *w1l, *w2h, *w2l;
    cudaGetSymbolAddress((void**)&qkv, g_qkv);
    cudaGetSymbolAddress((void**)&x2,  g_x2);
    cudaGetSymbolAddress((void**)&lnh, g_ln_hi); cudaGetSymbolAddress((void**)&lnl, g_ln_lo);
    cudaGetSymbolAddress((void**)&ath, g_at_hi); cudaGetSymbolAddress((void**)&atl, g_at_lo);
    cudaGetSymbolAddress((void**)&h1h, g_h1_hi); cudaGetSymbolAddress((void**)&h1l, g_h1_lo);
    cudaGetSymbolAddress((void**)&wqh, g_wqkv_hi); cudaGetSymbolAddress((void**)&wql, g_wqkv_lo);
    cudaGetSymbolAddress((void**)&woh, g_wout_hi); cudaGetSymbolAddress((void**)&wol, g_wout_lo);
    cudaGetSymbolAddress((void**)&w1h, g_w1_hi);   cudaGetSymbolAddress((void**)&w1l, g_w1_lo);
    cudaGetSymbolAddress((void**)&w2h, g_w2_hi);   cudaGetSymbolAddress((void**)&w2l, g_w2_lo);

    cudaFuncSetAttribute(attn_kernel, cudaFuncAttributeMaxDynamicSharedMemorySize, ATT_SMEM);
    cudaFuncSetAttribute(gemm_tc,     cudaFuncAttributeMaxDynamicSharedMemorySize, GT_SMEM);

    dim3 wb(32, 8);
    wconv_kernel<<<dim3(D_QKV / 32, D_MODEL / 32), wb>>>(w_qkv, wqh, wql, D_MODEL, D_QKV);
    wconv_kernel<<<dim3(D_MODEL / 32, D_MODEL / 32), wb>>>(w_out, woh, wol, D_MODEL, D_MODEL);
    wconv_kernel<<<dim3(D_FF / 32, D_MODEL / 32), wb>>>(w1, w1h, w1l, D_MODEL, D_FF);
    wconv_kernel<<<dim3(D_MODEL / 32, D_FF / 32), wb>>>(w2, w2h, w2l, D_FF, D_MODEL);

    ln_kernel<<<M_ROWS, 256>>>(x, ln1_g, ln1_b, lnh, lnl);
    gemm_tc<<<dim3(D_QKV / 128, M_ROWS / 128), 256, GT_SMEM>>>(
        lnh, lnl, wqh, wql, b_qkv, nullptr, qkv, nullptr, nullptr,
        M_ROWS, D_QKV, D_MODEL, 0);
    attn_kernel<<<dim3(2048 / 64, 2 * N_HEADS), 256, ATT_SMEM>>>(qkv, ath, atl);
    gemm_tc<<<dim3(D_MODEL / 128, M_ROWS / 128), 256, GT_SMEM>>>(
        ath, atl, woh, wol, b_out, x, x2, nullptr, nullptr,
        M_ROWS, D_MODEL, D_MODEL, 2);
    ln_kernel<<<M_ROWS, 256>>>(x2, ln2_g, ln2_b, lnh, lnl);
    gemm_tc<<<dim3(D_FF / 128, M_ROWS / 128), 256, GT_SMEM>>>(
        lnh, lnl, w1h, w1l, b1, nullptr, nullptr, h1h, h1l,
        M_ROWS, D_FF, D_MODEL, 1);
    gemm_tc<<<dim3(D_MODEL / 128, M_ROWS / 128), 256, GT_SMEM>>>(
        h1h, h1l, w2h, w2l, b2, x2, out, nullptr, nullptr,
        M_ROWS, D_MODEL, D_FF, 2);
}

// round 6
// speedup vs baseline: 2.4144x; 1.4814x over previous
#include <cuda_runtime.h>
#include <cuda_bf16.h>
#include <math.h>
#include <stdint.h>

// Problem: B=2, S=2048, D=1024, H=16, DH=64
#define M_ROWS 4096
#define D_MODEL 1024
#define D_QKV   3072
#define D_FF    4096
#define N_HEADS 16
#define D_HEAD  64

// ---------------- scratch (device globals; no allocation) ----------------
__device__ float g_qkv[M_ROWS * D_QKV];
__device__ float g_x2 [M_ROWS * D_MODEL];
__device__ unsigned short g_ln_hi[M_ROWS * D_MODEL], g_ln_lo[M_ROWS * D_MODEL];
__device__ unsigned short g_at_hi[M_ROWS * D_MODEL], g_at_lo[M_ROWS * D_MODEL];
__device__ unsigned short g_h1_hi[M_ROWS * D_FF],    g_h1_lo[M_ROWS * D_FF];
__device__ unsigned short g_wqkv_hi[D_QKV * D_MODEL], g_wqkv_lo[D_QKV * D_MODEL];
__device__ unsigned short g_wout_hi[D_MODEL * D_MODEL], g_wout_lo[D_MODEL * D_MODEL];
__device__ unsigned short g_w1_hi[D_FF * D_MODEL],   g_w1_lo[D_FF * D_MODEL];
__device__ unsigned short g_w2_hi[D_MODEL * D_FF],   g_w2_lo[D_MODEL * D_FF];

// ---------------- helpers (baseline sm_80+ features only) ----------------
__device__ __forceinline__ uint32_t smem_u32(const void* p) {
    uint32_t a;
    asm("{ .reg .u64 t; cvta.to.shared.u64 t, %1; cvt.u32.u64 %0, t; }" : "=r"(a) : "l"(p));
    return a;
}
__device__ __forceinline__ void cp16(uint32_t dst, const void* src) {
    asm volatile("cp.async.cg.shared.global [%0], [%1], 16;" :: "r"(dst), "l"(src));
}
#define CP_COMMIT() asm volatile("cp.async.commit_group;" ::: "memory")
#define CP_WAIT1()  asm volatile("cp.async.wait_group 1;" ::: "memory")
#define CP_WAIT0()  asm volatile("cp.async.wait_group 0;" ::: "memory")

#define LDSM_X4(r0, r1, r2, r3, addr) \
    asm volatile("ldmatrix.sync.aligned.m8n8.x4.shared.b16 {%0,%1,%2,%3}, [%4];" \
        : "=r"(r0), "=r"(r1), "=r"(r2), "=r"(r3) : "r"(addr))

#define LDSM_X4_T(r0, r1, r2, r3, addr) \
    asm volatile("ldmatrix.sync.aligned.m8n8.x4.trans.shared.b16 {%0,%1,%2,%3}, [%4];" \
        : "=r"(r0), "=r"(r1), "=r"(r2), "=r"(r3) : "r"(addr))

#define MMA16816(c, a, b) \
    asm volatile("mma.sync.aligned.m16n8k16.row.col.f32.bf16.bf16.f32 " \
        "{%0,%1,%2,%3}, {%4,%5,%6,%7}, {%8,%9}, {%0,%1,%2,%3};" \
        : "+f"((c)[0]), "+f"((c)[1]), "+f"((c)[2]), "+f"((c)[3]) \
        : "r"((a)[0]), "r"((a)[1]), "r"((a)[2]), "r"((a)[3]), "r"((b)[0]), "r"((b)[1]))

__device__ __forceinline__ float gelu_exact(float v) {
    return 0.5f * v * (1.0f + erff(v * 0.70710678118654752f));
}
__device__ __forceinline__ void split_bf16(float v, unsigned short& hi, unsigned short& lo) {
    __nv_bfloat16 h = __float2bfloat16(v);
    float r = v - __bfloat162float(h);
    hi = __bfloat16_as_ushort(h);
    lo = __bfloat16_as_ushort(__float2bfloat16(r));
}
// pack two floats into hi/lo bf16x2 words
__device__ __forceinline__ void split_pack2(float x, float y, uint32_t& whi, uint32_t& wlo) {
    unsigned short hx, lx, hy, ly;
    split_bf16(x, hx, lx); split_bf16(y, hy, ly);
    whi = (uint32_t)hx | ((uint32_t)hy << 16);
    wlo = (uint32_t)lx | ((uint32_t)ly << 16);
}

// ================= weight transpose + bf16 hi/lo split =================
__global__ void wconv_kernel(const float* __restrict__ W,
                             unsigned short* __restrict__ Thi,
                             unsigned short* __restrict__ Tlo, int K, int N)
{
    __shared__ float t[32][33];
    int n0 = blockIdx.x * 32, k0 = blockIdx.y * 32;
    int tx = threadIdx.x, ty = threadIdx.y;
    #pragma unroll
    for (int i = 0; i < 32; i += 8)
        t[ty + i][tx] = W[(size_t)(k0 + ty + i) * N + n0 + tx];
    __syncthreads();
    #pragma unroll
    for (int i = 0; i < 32; i += 8) {
        float v = t[tx][ty + i];
        unsigned short h, l;
        split_bf16(v, h, l);
        size_t o = (size_t)(n0 + ty + i) * K + k0 + tx;
        Thi[o] = h; Tlo[o] = l;
    }
}

// ================= LayerNorm (writes bf16 hi/lo) =================
__global__ __launch_bounds__(256) void ln_kernel(
    const float* __restrict__ x, const float* __restrict__ g,
    const float* __restrict__ b,
    unsigned short* __restrict__ yhi, unsigned short* __restrict__ ylo)
{
    int row = blockIdx.x;
    const float* xr = x + (size_t)row * D_MODEL;
    int tid = threadIdx.x;
    float4 v = *(const float4*)(xr + tid * 4);
    float s = v.x + v.y + v.z + v.w;
    float q = v.x*v.x + v.y*v.y + v.z*v.z + v.w*v.w;
    #pragma unroll
    for (int off = 16; off > 0; off >>= 1) {
        s += __shfl_xor_sync(0xffffffffu, s, off);
        q += __shfl_xor_sync(0xffffffffu, q, off);
    }
    __shared__ float sh_s[8], sh_q[8];
    int w = tid >> 5, lane = tid & 31;
    if (lane == 0) { sh_s[w] = s; sh_q[w] = q; }
    __syncthreads();
    if (tid == 0) {
        float ts = 0.f, tq = 0.f;
        #pragma unroll
        for (int i = 0; i < 8; i++) { ts += sh_s[i]; tq += sh_q[i]; }
        sh_s[0] = ts; sh_q[0] = tq;
    }
    __syncthreads();
    float mean = sh_s[0] * (1.f / D_MODEL);
    float var  = sh_q[0] * (1.f / D_MODEL) - mean * mean;
    float rstd = rsqrtf(var + 1e-5f);
    float4 gv = *(const float4*)(g + tid * 4);
    float4 bv = *(const float4*)(b + tid * 4);
    float o0 = (v.x - mean) * rstd * gv.x + bv.x;
    float o1 = (v.y - mean) * rstd * gv.y + bv.y;
    float o2 = (v.z - mean) * rstd * gv.z + bv.z;
    float o3 = (v.w - mean) * rstd * gv.w + bv.w;
    uint32_t h01, l01, h23, l23;
    split_pack2(o0, o1, h01, l01);
    split_pack2(o2, o3, h23, l23);
    size_t off = (size_t)row * D_MODEL + tid * 4;
    *(uint2*)(yhi + off) = make_uint2(h01, h23);
    *(uint2*)(ylo + off) = make_uint2(l01, l23);
}

// ================= HMMA bf16x3 GEMM (unchanged from R5) =================
#define GSTAGE 40960
#define GT_SMEM (2 * GSTAGE)

__global__ __launch_bounds__(256, 1) void gemm_tc(
    const unsigned short* __restrict__ Ahi, const unsigned short* __restrict__ Alo,
    const unsigned short* __restrict__ Bhi, const unsigned short* __restrict__ Blo,
    const float* __restrict__ bias, const float* __restrict__ res,
    float* __restrict__ outf,
    unsigned short* __restrict__ ohi, unsigned short* __restrict__ olo,
    int M, int N, int K, int mode)
{
    extern __shared__ char smem[];
    const uint32_t sb = smem_u32(smem);
    const int tid = threadIdx.x;
    const int wid = tid >> 5, lane = tid & 31;
    const int wr = wid >> 2, wc = wid & 3;
    const int row0 = blockIdx.y * 128, col0 = blockIdx.x * 128;

    const int lr = tid >> 2;
    const int lj = tid & 3;

    float c[4][4][4];
    #pragma unroll
    for (int mt = 0; mt < 4; mt++)
        #pragma unroll
        for (int nt = 0; nt < 4; nt++)
            #pragma unroll
            for (int i = 0; i < 4; i++) c[mt][nt][i] = 0.f;

    const int nch = K >> 5;

    auto issue = [&](int cc, int s) {
        const int k0 = cc * 32;
        const uint32_t base = sb + (uint32_t)s * GSTAGE;
        const uint32_t ro = (uint32_t)lr * 80u + (uint32_t)lj * 16u;
        const size_t asrc = (size_t)(row0 + lr) * K + k0 + lj * 8;
        const size_t bsrc = (size_t)(col0 + lr) * K + k0 + lj * 8;
        const size_t step = (size_t)64 * K;
        cp16(base +          ro,            Ahi + asrc);
        cp16(base +          ro + 64 * 80u, Ahi + asrc + step);
        cp16(base + 10240u + ro,            Alo + asrc);
        cp16(base + 10240u + ro + 64 * 80u, Alo + asrc + step);
        cp16(base + 20480u + ro,            Bhi + bsrc);
        cp16(base + 20480u + ro + 64 * 80u, Bhi + bsrc + step);
        cp16(base + 30720u + ro,            Blo + bsrc);
        cp16(base + 30720u + ro + 64 * 80u, Blo + bsrc + step);
    };

    issue(0, 0);
    CP_COMMIT();

    for (int cc = 0; cc < nch; cc++) {
        const int s = cc & 1;
        if (cc + 1 < nch) { issue(cc + 1, s ^ 1); CP_COMMIT(); CP_WAIT1(); }
        else              { CP_WAIT0(); }
        __syncthreads();

        const uint32_t base = sb + (uint32_t)s * GSTAGE;
        const uint32_t aHiB = base;
        const uint32_t aLoB = base + 10240u;
        const uint32_t bHiB = base + 20480u;
        const uint32_t bLoB = base + 30720u;

        #pragma unroll
        for (int kk = 0; kk < 32; kk += 16) {
            uint32_t a[4][4], bh[4][2], bl[4][2];
            const uint32_t acol = (uint32_t)((kk + ((lane >> 4) << 3)) << 1);
            const uint32_t arow = (uint32_t)(wr * 64 + (lane & 15)) * 80u;
            #pragma unroll
            for (int mt = 0; mt < 4; mt++)
                LDSM_X4(a[mt][0], a[mt][1], a[mt][2], a[mt][3],
                        aHiB + arow + (uint32_t)(mt * 16) * 80u + acol);
            {
                const int g = lane >> 3;
                const int rn = (g >= 2) ? 8 : 0;
                const uint32_t bcol = (uint32_t)((kk + ((g & 1) << 3)) << 1);
                const uint32_t brow = (uint32_t)(wc * 32 + rn + (lane & 7)) * 80u;
                #pragma unroll
                for (int nt2 = 0; nt2 < 2; nt2++)
                    LDSM_X4(bh[nt2*2][0], bh[nt2*2][1], bh[nt2*2+1][0], bh[nt2*2+1][1],
                            bHiB + brow + (uint32_t)(nt2 * 16) * 80u + bcol);
                #pragma unroll
                for (int nt2 = 0; nt2 < 2; nt2++)
                    LDSM_X4(bl[nt2*2][0], bl[nt2*2][1], bl[nt2*2+1][0], bl[nt2*2+1][1],
                            bLoB + brow + (uint32_t)(nt2 * 16) * 80u + bcol);
            }
            #pragma unroll
            for (int mt = 0; mt < 4; mt++)
                #pragma unroll
                for (int nt = 0; nt < 4; nt++)
                    MMA16816(c[mt][nt], a[mt], bh[nt]);
            #pragma unroll
            for (int mt = 0; mt < 4; mt++)
                #pragma unroll
                for (int nt = 0; nt < 4; nt++)
                    MMA16816(c[mt][nt], a[mt], bl[nt]);
            #pragma unroll
            for (int mt = 0; mt < 4; mt++)
                LDSM_X4(a[mt][0], a[mt][1], a[mt][2], a[mt][3],
                        aLoB + arow + (uint32_t)(mt * 16) * 80u + acol);
            #pragma unroll
            for (int mt = 0; mt < 4; mt++)
                #pragma unroll
                for (int nt = 0; nt < 4; nt++)
                    MMA16816(c[mt][nt], a[mt], bh[nt]);
        }
        __syncthreads();
    }

    #pragma unroll
    for (int mt = 0; mt < 4; mt++) {
        #pragma unroll
        for (int nt = 0; nt < 4; nt++) {
            const int r = row0 + wr * 64 + mt * 16 + (lane >> 2);
            const int ccol = col0 + wc * 32 + nt * 8 + ((lane & 3) << 1);
            const float b0 = bias[ccol], b1 = bias[ccol + 1];
            #pragma unroll
            for (int hh = 0; hh < 2; hh++) {
                const int rr = r + hh * 8;
                float v0 = c[mt][nt][hh * 2 + 0] + b0;
                float v1 = c[mt][nt][hh * 2 + 1] + b1;
                if (mode == 1) {
                    v0 = gelu_exact(v0); v1 = gelu_exact(v1);
                    uint32_t wh, wl;
                    split_pack2(v0, v1, wh, wl);
                    *(uint32_t*)(ohi + (size_t)rr * N + ccol) = wh;
                    *(uint32_t*)(olo + (size_t)rr * N + ccol) = wl;
                } else {
                    if (mode == 2) {
                        float2 rv = *(const float2*)(res + (size_t)rr * N + ccol);
                        v0 += rv.x; v1 += rv.y;
                    }
                    *(float2*)(outf + (size_t)rr * N + ccol) = make_float2(v0, v1);
                }
            }
        }
    }
}

// ================= HMMA bf16x3 Flash Attention =================
// Block: one (b,h), 128 q-rows. 256 threads = 8 warps, warp = 16 q-rows.
// SMEM (ushort counts): qhi[128*72], qlo[128*72], khi[64*72], klo[64*72],
//                        vhi[64*72], vlo[64*72].  72 = 64 + 8 pad. Total 73728 B.
#define ASTR 72
#define AQ_H 0
#define AQ_L (128 * ASTR)
#define AK_H (2 * 128 * ASTR)
#define AK_L (AK_H + 64 * ASTR)
#define AV_H (AK_L + 64 * ASTR)
#define AV_L (AV_H + 64 * ASTR)
#define ATT2_SMEM ((AV_L + 64 * ASTR) * 2)

__global__ __launch_bounds__(256) void attn_mma(
    const float* __restrict__ qkv,
    unsigned short* __restrict__ ohi, unsigned short* __restrict__ olo)
{
    extern __shared__ unsigned short asmem[];
    const uint32_t sB = smem_u32(asmem);
    const int tid = threadIdx.x;
    const int wid = tid >> 5, lane = tid & 31;
    const int bh = blockIdx.y;
    const int b = bh >> 4, h = bh & 15;
    const int q0 = blockIdx.x * 128;

    const float* qbase = qkv + (size_t)b * 2048 * D_QKV + h * D_HEAD;
    const float* kbase = qbase + D_MODEL;
    const float* vbase = qbase + 2 * D_MODEL;

    // ---- load Q tile (128x64), scale by 1/8, split to hi/lo ----
    {
        const int colb = (tid & 3) * 16;
        #pragma unroll
        for (int i = 0; i < 2; i++) {
            const int row = (tid >> 2) + i * 64;
            const float* src = qbase + (size_t)(q0 + row) * D_QKV + colb;
            #pragma unroll
            for (int u = 0; u < 4; u++) {
                float4 v = *(const float4*)(src + u * 4);
                v.x *= 0.125f; v.y *= 0.125f; v.z *= 0.125f; v.w *= 0.125f;
                uint32_t h01, l01, h23, l23;
                split_pack2(v.x, v.y, h01, l01);
                split_pack2(v.z, v.w, h23, l23);
                const int o = row * ASTR + colb + u * 4;
                *(uint2*)(asmem + AQ_H + o) = make_uint2(h01, h23);
                *(uint2*)(asmem + AQ_L + o) = make_uint2(l01, l23);
            }
        }
    }

    float cO[8][4];
    #pragma unroll
    for (int nt = 0; nt < 8; nt++)
        #pragma unroll
        for (int i = 0; i < 4; i++) cO[nt][i] = 0.f;
    float m2[2] = {-1e30f, -1e30f};
    float l2[2] = {0.f, 0.f};

    const uint32_t qhB = sB + AQ_H * 2, qlB = sB + AQ_L * 2;
    const uint32_t khB = sB + AK_H * 2, klB = sB + AK_L * 2;
    const uint32_t vhB = sB + AV_H * 2, vlB = sB + AV_L * 2;

    for (int kt = 0; kt < 2048; kt += 64) {
        // ---- load K,V tile (64x64 each), split ----
        {
            const int row = tid >> 2;
            const int colb = (tid & 3) * 16;
            const float* ks = kbase + (size_t)(kt + row) * D_QKV + colb;
            const float* vs = vbase + (size_t)(kt + row) * D_QKV + colb;
            #pragma unroll
            for (int u = 0; u < 4; u++) {
                float4 kv = *(const float4*)(ks + u * 4);
                uint32_t h01, l01, h23, l23;
                split_pack2(kv.x, kv.y, h01, l01);
                split_pack2(kv.z, kv.w, h23, l23);
                const int o = row * ASTR + colb + u * 4;
                *(uint2*)(asmem + AK_H + o) = make_uint2(h01, h23);
                *(uint2*)(asmem + AK_L + o) = make_uint2(l01, l23);
                float4 vv = *(const float4*)(vs + u * 4);
                split_pack2(vv.x, vv.y, h01, l01);
                split_pack2(vv.z, vv.w, h23, l23);
                *(uint2*)(asmem + AV_H + o) = make_uint2(h01, h23);
                *(uint2*)(asmem + AV_L + o) = make_uint2(l01, l23);
            }
        }
        __syncthreads();

        // ---- S = Q K^T (bf16x3), warp rows wid*16..+15, cols 0..63 ----
        float cS[8][4];
        #pragma unroll
        for (int nt = 0; nt < 8; nt++)
            #pragma unroll
            for (int i = 0; i < 4; i++) cS[nt][i] = 0.f;

        const uint32_t arow = (uint32_t)(wid * 16 + (lane & 15)) * (ASTR * 2);
        const int g = lane >> 3;
        const int rn = (g >= 2) ? 8 : 0;
        #pragma unroll
        for (int kk = 0; kk < 4; kk++) {
            const uint32_t acol = (uint32_t)((kk * 16 + ((lane >> 4) << 3)) << 1);
            uint32_t ah[4], al[4];
            LDSM_X4(ah[0], ah[1], ah[2], ah[3], qhB + arow + acol);
            LDSM_X4(al[0], al[1], al[2], al[3], qlB + arow + acol);
            const uint32_t bcol = (uint32_t)((kk * 16 + ((g & 1) << 3)) << 1);
            #pragma unroll
            for (int nt2 = 0; nt2 < 4; nt2++) {
                const uint32_t brow = (uint32_t)(nt2 * 16 + rn + (lane & 7)) * (ASTR * 2);
                uint32_t bhf[4], blf[4];
                LDSM_X4(bhf[0], bhf[1], bhf[2], bhf[3], khB + brow + bcol);
                LDSM_X4(blf[0], blf[1], blf[2], blf[3], klB + brow + bcol);
                MMA16816(cS[nt2*2],   ah, bhf);
                MMA16816(cS[nt2*2+1], ah, bhf + 2);
                MMA16816(cS[nt2*2],   ah, blf);
                MMA16816(cS[nt2*2+1], ah, blf + 2);
                MMA16816(cS[nt2*2],   al, bhf);
                MMA16816(cS[nt2*2+1], al, bhf + 2);
            }
        }

        // ---- online softmax on cS (rows: lane>>2 and +8; quad = lanes sharing lane>>2) ----
        #pragma unroll
        for (int hh = 0; hh < 2; hh++) {
            float mx = cS[0][hh*2];
            #pragma unroll
            for (int nt = 0; nt < 8; nt++) {
                mx = fmaxf(mx, cS[nt][hh*2]);
                mx = fmaxf(mx, cS[nt][hh*2+1]);
            }
            mx = fmaxf(mx, __shfl_xor_sync(0xffffffffu, mx, 1));
            mx = fmaxf(mx, __shfl_xor_sync(0xffffffffu, mx, 2));
            const float mnew = fmaxf(m2[hh], mx);
            const float corr = __expf(m2[hh] - mnew);
            m2[hh] = mnew;
            float sum = 0.f;
            #pragma unroll
            for (int nt = 0; nt < 8; nt++) {
                float p0 = __expf(cS[nt][hh*2]   - mnew);
                float p1 = __expf(cS[nt][hh*2+1] - mnew);
                cS[nt][hh*2] = p0; cS[nt][hh*2+1] = p1;
                sum += p0 + p1;
            }
            sum += __shfl_xor_sync(0xffffffffu, sum, 1);
            sum += __shfl_xor_sync(0xffffffffu, sum, 2);
            l2[hh] = l2[hh] * corr + sum;
            #pragma unroll
            for (int nt = 0; nt < 8; nt++) {
                cO[nt][hh*2]   *= corr;
                cO[nt][hh*2+1] *= corr;
            }
        }

        // ---- O += P V (bf16x3); P A-frags packed from cS ----
        const int tt = lane >> 3;
        const uint32_t vrow0 = (uint32_t)(((tt & 1) << 3) + (lane & 7)) * (ASTR * 2);
        const uint32_t vcoff = (uint32_t)((tt >> 1) << 3) * 2;
        #pragma unroll
        for (int kk2 = 0; kk2 < 4; kk2++) {
            uint32_t ahi[4], alo[4];
            split_pack2(cS[2*kk2][0],   cS[2*kk2][1],   ahi[0], alo[0]);
            split_pack2(cS[2*kk2][2],   cS[2*kk2][3],   ahi[1], alo[1]);
            split_pack2(cS[2*kk2+1][0], cS[2*kk2+1][1], ahi[2], alo[2]);
            split_pack2(cS[2*kk2+1][2], cS[2*kk2+1][3], ahi[3], alo[3]);
            const uint32_t vrow = vrow0 + (uint32_t)(kk2 * 16) * (ASTR * 2);
            #pragma unroll
            for (int nt2 = 0; nt2 < 4; nt2++) {
                const uint32_t vcol = (uint32_t)(nt2 * 16) * 2 + vcoff;
                uint32_t bvh[4], bvl[4];
                LDSM_X4_T(bvh[0], bvh[1], bvh[2], bvh[3], vhB + vrow + vcol);
                LDSM_X4_T(bvl[0], bvl[1], bvl[2], bvl[3], vlB + vrow + vcol);
                MMA16816(cO[nt2*2],   ahi, bvh);
                MMA16816(cO[nt2*2+1], ahi, bvh + 2);
                MMA16816(cO[nt2*2],   ahi, bvl);
                MMA16816(cO[nt2*2+1], ahi, bvl + 2);
                MMA16816(cO[nt2*2],   alo, bvh);
                MMA16816(cO[nt2*2+1], alo, bvh + 2);
            }
        }
        __syncthreads();
    }

    // ---- epilogue: O /= l, split to hi/lo, write [B*S, D] at col h*64 ----
    #pragma unroll
    for (int hh = 0; hh < 2; hh++) {
        const float inv = 1.0f / l2[hh];
        const int row = q0 + wid * 16 + (lane >> 2) + hh * 8;
        const size_t rbase = ((size_t)b * 2048 + row) * D_MODEL + h * D_HEAD + ((lane & 3) << 1);
        #pragma unroll
        for (int nt = 0; nt < 8; nt++) {
            float v0 = cO[nt][hh*2]   * inv;
            float v1 = cO[nt][hh*2+1] * inv;
            uint32_t wh, wl;
            split_pack2(v0, v1, wh, wl);
            *(uint32_t*)(ohi + rbase + nt * 8) = wh;
            *(uint32_t*)(olo + rbase + nt * 8) = wl;
        }
    }
}

// ================= launch =================
extern "C" void kernel_launch(void* const* d_in, const int* in_sizes, int n_in,
                              void* d_out, int out_size)
{
    (void)in_sizes; (void)n_in; (void)out_size;
    const float* x     = (const float*)d_in[0];
    const float* ln1_g = (const float*)d_in[1];
    const float* ln1_b = (const float*)d_in[2];
    const float* w_qkv = (const float*)d_in[3];
    const float* b_qkv = (const float*)d_in[4];
    const float* w_out = (const float*)d_in[5];
    const float* b_out = (const float*)d_in[6];
    const float* ln2_g = (const float*)d_in[7];
    const float* ln2_b = (const float*)d_in[8];
    const float* w1    = (const float*)d_in[9];
    const float* b1    = (const float*)d_in[10];
    const float* w2    = (const float*)d_in[11];
    const float* b2    = (const float*)d_in[12];
    float* out = (float*)d_out;

    float *qkv, *x2;
    unsigned short *lnh, *lnl, *ath, *atl, *h1h, *h1l;
    unsigned short *wqh, *wql, *woh, *wol, *w1h, *w1l, *w2h, *w2l;
    cudaGetSymbolAddress((void**)&qkv, g_qkv);
    cudaGetSymbolAddress((void**)&x2,  g_x2);
    cudaGetSymbolAddress((void**)&lnh, g_ln_hi); cudaGetSymbolAddress((void**)&lnl, g_ln_lo);
    cudaGetSymbolAddress((void**)&ath, g_at_hi); cudaGetSymbolAddress((void**)&atl, g_at_lo);
    cudaGetSymbolAddress((void**)&h1h, g_h1_hi); cudaGetSymbolAddress((void**)&h1l, g_h1_lo);
    cudaGetSymbolAddress((void**)&wqh, g_wqkv_hi); cudaGetSymbolAddress((void**)&wql, g_wqkv_lo);
    cudaGetSymbolAddress((void**)&woh, g_wout_hi); cudaGetSymbolAddress((void**)&wol, g_wout_lo);
    cudaGetSymbolAddress((void**)&w1h, g_w1_hi);   cudaGetSymbolAddress((void**)&w1l, g_w1_lo);
    cudaGetSymbolAddress((void**)&w2h, g_w2_hi);   cudaGetSymbolAddress((void**)&w2l, g_w2_lo);

    cudaFuncSetAttribute(attn_mma, cudaFuncAttributeMaxDynamicSharedMemorySize, ATT2_SMEM);
    cudaFuncSetAttribute(gemm_tc,  cudaFuncAttributeMaxDynamicSharedMemorySize, GT_SMEM);

    dim3 wb(32, 8);
    wconv_kernel<<<dim3(D_QKV / 32, D_MODEL / 32), wb>>>(w_qkv, wqh, wql, D_MODEL, D_QKV);
    wconv_kernel<<<dim3(D_MODEL / 32, D_MODEL / 32), wb>>>(w_out, woh, wol, D_MODEL, D_MODEL);
    wconv_kernel<<<dim3(D_FF / 32, D_MODEL / 32), wb>>>(w1, w1h, w1l, D_MODEL, D_FF);
    wconv_kernel<<<dim3(D_MODEL / 32, D_FF / 32), wb>>>(w2, w2h, w2l, D_FF, D_MODEL);

    ln_kernel<<<M_ROWS, 256>>>(x, ln1_g, ln1_b, lnh, lnl);
    gemm_tc<<<dim3(D_QKV / 128, M_ROWS / 128), 256, GT_SMEM>>>(
        lnh, lnl, wqh, wql, b_qkv, nullptr, qkv, nullptr, nullptr,
        M_ROWS, D_QKV, D_MODEL, 0);
    attn_mma<<<dim3(2048 / 128, 2 * N_HEADS), 256, ATT2_SMEM>>>(qkv, ath, atl);
    gemm_tc<<<dim3(D_MODEL / 128, M_ROWS / 128), 256, GT_SMEM>>>(
        ath, atl, woh, wol, b_out, x, x2, nullptr, nullptr,
        M_ROWS, D_MODEL, D_MODEL, 2);
    ln_kernel<<<M_ROWS, 256>>>(x2, ln2_g, ln2_b, lnh, lnl);
    gemm_tc<<<dim3(D_FF / 128, M_ROWS / 128), 256, GT_SMEM>>>(
        lnh, lnl, w1h, w1l, b1, nullptr, nullptr, h1h, h1l,
        M_ROWS, D_FF, D_MODEL, 1);
    gemm_tc<<<dim3(D_MODEL / 128, M_ROWS / 128), 256, GT_SMEM>>>(
        h1h, h1l, w2h, w2l, b2, x2, out, nullptr, nullptr,
        M_ROWS, D_MODEL, D_FF, 2);
}

// round 7
// speedup vs baseline: 2.6902x; 1.1143x over previous
#include <cuda_runtime.h>
#include <cuda_bf16.h>
#include <math.h>
#include <stdint.h>

// Problem: B=2, S=2048, D=1024, H=16, DH=64
#define M_ROWS 4096
#define D_MODEL 1024
#define D_QKV   3072
#define D_FF    4096
#define N_HEADS 16
#define D_HEAD  64

// ---------------- scratch (device globals; no allocation) ----------------
__device__ float g_qkv[M_ROWS * D_QKV];
__device__ float g_x2 [M_ROWS * D_MODEL];
__device__ unsigned short g_ln_hi[M_ROWS * D_MODEL], g_ln_lo[M_ROWS * D_MODEL];
__device__ unsigned short g_at_hi[M_ROWS * D_MODEL], g_at_lo[M_ROWS * D_MODEL];
__device__ unsigned short g_h1_hi[M_ROWS * D_FF],    g_h1_lo[M_ROWS * D_FF];
__device__ unsigned short g_wqkv_hi[D_QKV * D_MODEL], g_wqkv_lo[D_QKV * D_MODEL];
__device__ unsigned short g_wout_hi[D_MODEL * D_MODEL], g_wout_lo[D_MODEL * D_MODEL];
__device__ unsigned short g_w1_hi[D_FF * D_MODEL],   g_w1_lo[D_FF * D_MODEL];
__device__ unsigned short g_w2_hi[D_MODEL * D_FF],   g_w2_lo[D_MODEL * D_FF];

// ---------------- helpers ----------------
__device__ __forceinline__ uint32_t smem_u32(const void* p) {
    uint32_t a;
    asm("{ .reg .u64 t; cvta.to.shared.u64 t, %1; cvt.u32.u64 %0, t; }" : "=r"(a) : "l"(p));
    return a;
}
__device__ __forceinline__ void cp16(uint32_t dst, const void* src) {
    asm volatile("cp.async.cg.shared.global [%0], [%1], 16;" :: "r"(dst), "l"(src));
}
#define CP_COMMIT() asm volatile("cp.async.commit_group;" ::: "memory")
#define CP_WAIT1()  asm volatile("cp.async.wait_group 1;" ::: "memory")
#define CP_WAIT0()  asm volatile("cp.async.wait_group 0;" ::: "memory")

#define LDSM_X4(r0, r1, r2, r3, addr) \
    asm volatile("ldmatrix.sync.aligned.m8n8.x4.shared.b16 {%0,%1,%2,%3}, [%4];" \
        : "=r"(r0), "=r"(r1), "=r"(r2), "=r"(r3) : "r"(addr))

#define LDSM_X4_T(r0, r1, r2, r3, addr) \
    asm volatile("ldmatrix.sync.aligned.m8n8.x4.trans.shared.b16 {%0,%1,%2,%3}, [%4];" \
        : "=r"(r0), "=r"(r1), "=r"(r2), "=r"(r3) : "r"(addr))

#define MMA16816(c, a, b) \
    asm volatile("mma.sync.aligned.m16n8k16.row.col.f32.bf16.bf16.f32 " \
        "{%0,%1,%2,%3}, {%4,%5,%6,%7}, {%8,%9}, {%0,%1,%2,%3};" \
        : "+f"((c)[0]), "+f"((c)[1]), "+f"((c)[2]), "+f"((c)[3]) \
        : "r"((a)[0]), "r"((a)[1]), "r"((a)[2]), "r"((a)[3]), "r"((b)[0]), "r"((b)[1]))

__device__ __forceinline__ float gelu_exact(float v) {
    return 0.5f * v * (1.0f + erff(v * 0.70710678118654752f));
}
__device__ __forceinline__ void split_bf16(float v, unsigned short& hi, unsigned short& lo) {
    __nv_bfloat16 h = __float2bfloat16(v);
    float r = v - __bfloat162float(h);
    hi = __bfloat16_as_ushort(h);
    lo = __bfloat16_as_ushort(__float2bfloat16(r));
}
__device__ __forceinline__ void split_pack2(float x, float y, uint32_t& whi, uint32_t& wlo) {
    unsigned short hx, lx, hy, ly;
    split_bf16(x, hx, lx); split_bf16(y, hy, ly);
    whi = (uint32_t)hx | ((uint32_t)hy << 16);
    wlo = (uint32_t)lx | ((uint32_t)ly << 16);
}

// ================= weight transpose + bf16 hi/lo split =================
__global__ void wconv_kernel(const float* __restrict__ W,
                             unsigned short* __restrict__ Thi,
                             unsigned short* __restrict__ Tlo, int K, int N)
{
    __shared__ float t[32][33];
    int n0 = blockIdx.x * 32, k0 = blockIdx.y * 32;
    int tx = threadIdx.x, ty = threadIdx.y;
    #pragma unroll
    for (int i = 0; i < 32; i += 8)
        t[ty + i][tx] = W[(size_t)(k0 + ty + i) * N + n0 + tx];
    __syncthreads();
    #pragma unroll
    for (int i = 0; i < 32; i += 8) {
        float v = t[tx][ty + i];
        unsigned short h, l;
        split_bf16(v, h, l);
        size_t o = (size_t)(n0 + ty + i) * K + k0 + tx;
        Thi[o] = h; Tlo[o] = l;
    }
}

// ================= LayerNorm (writes bf16 hi/lo) =================
__global__ __launch_bounds__(256) void ln_kernel(
    const float* __restrict__ x, const float* __restrict__ g,
    const float* __restrict__ b,
    unsigned short* __restrict__ yhi, unsigned short* __restrict__ ylo)
{
    int row = blockIdx.x;
    const float* xr = x + (size_t)row * D_MODEL;
    int tid = threadIdx.x;
    float4 v = *(const float4*)(xr + tid * 4);
    float s = v.x + v.y + v.z + v.w;
    float q = v.x*v.x + v.y*v.y + v.z*v.z + v.w*v.w;
    #pragma unroll
    for (int off = 16; off > 0; off >>= 1) {
        s += __shfl_xor_sync(0xffffffffu, s, off);
        q += __shfl_xor_sync(0xffffffffu, q, off);
    }
    __shared__ float sh_s[8], sh_q[8];
    int w = tid >> 5, lane = tid & 31;
    if (lane == 0) { sh_s[w] = s; sh_q[w] = q; }
    __syncthreads();
    if (tid == 0) {
        float ts = 0.f, tq = 0.f;
        #pragma unroll
        for (int i = 0; i < 8; i++) { ts += sh_s[i]; tq += sh_q[i]; }
        sh_s[0] = ts; sh_q[0] = tq;
    }
    __syncthreads();
    float mean = sh_s[0] * (1.f / D_MODEL);
    float var  = sh_q[0] * (1.f / D_MODEL) - mean * mean;
    float rstd = rsqrtf(var + 1e-5f);
    float4 gv = *(const float4*)(g + tid * 4);
    float4 bv = *(const float4*)(b + tid * 4);
    float o0 = (v.x - mean) * rstd * gv.x + bv.x;
    float o1 = (v.y - mean) * rstd * gv.y + bv.y;
    float o2 = (v.z - mean) * rstd * gv.z + bv.z;
    float o3 = (v.w - mean) * rstd * gv.w + bv.w;
    uint32_t h01, l01, h23, l23;
    split_pack2(o0, o1, h01, l01);
    split_pack2(o2, o3, h23, l23);
    size_t off = (size_t)row * D_MODEL + tid * 4;
    *(uint2*)(yhi + off) = make_uint2(h01, h23);
    *(uint2*)(ylo + off) = make_uint2(l01, l23);
}

// ================= HMMA bf16x3 GEMM =================
// 2 CTAs/SM (regs capped at 128), fragments preloaded per kk-step.
#define GSTAGE 40960
#define GT_SMEM (2 * GSTAGE)

__global__ __launch_bounds__(256, 2) void gemm_tc(
    const unsigned short* __restrict__ Ahi, const unsigned short* __restrict__ Alo,
    const unsigned short* __restrict__ Bhi, const unsigned short* __restrict__ Blo,
    const float* __restrict__ bias, const float* __restrict__ res,
    float* __restrict__ outf,
    unsigned short* __restrict__ ohi, unsigned short* __restrict__ olo,
    int M, int N, int K, int mode)
{
    extern __shared__ char smem[];
    const uint32_t sb = smem_u32(smem);
    const int tid = threadIdx.x;
    const int wid = tid >> 5, lane = tid & 31;
    const int wr = wid >> 2, wc = wid & 3;
    const int row0 = blockIdx.y * 128, col0 = blockIdx.x * 128;

    const int lr = tid >> 2;
    const int lj = tid & 3;

    float c[4][4][4];
    #pragma unroll
    for (int mt = 0; mt < 4; mt++)
        #pragma unroll
        for (int nt = 0; nt < 4; nt++)
            #pragma unroll
            for (int i = 0; i < 4; i++) c[mt][nt][i] = 0.f;

    const int nch = K >> 5;

    auto issue = [&](int cc, int s) {
        const int k0 = cc * 32;
        const uint32_t base = sb + (uint32_t)s * GSTAGE;
        const uint32_t ro = (uint32_t)lr * 80u + (uint32_t)lj * 16u;
        const size_t asrc = (size_t)(row0 + lr) * K + k0 + lj * 8;
        const size_t bsrc = (size_t)(col0 + lr) * K + k0 + lj * 8;
        const size_t step = (size_t)64 * K;
        cp16(base +          ro,            Ahi + asrc);
        cp16(base +          ro + 64 * 80u, Ahi + asrc + step);
        cp16(base + 10240u + ro,            Alo + asrc);
        cp16(base + 10240u + ro + 64 * 80u, Alo + asrc + step);
        cp16(base + 20480u + ro,            Bhi + bsrc);
        cp16(base + 20480u + ro + 64 * 80u, Bhi + bsrc + step);
        cp16(base + 30720u + ro,            Blo + bsrc);
        cp16(base + 30720u + ro + 64 * 80u, Blo + bsrc + step);
    };

    issue(0, 0);
    CP_COMMIT();

    for (int cc = 0; cc < nch; cc++) {
        const int s = cc & 1;
        if (cc + 1 < nch) { issue(cc + 1, s ^ 1); CP_COMMIT(); CP_WAIT1(); }
        else              { CP_WAIT0(); }
        __syncthreads();

        const uint32_t base = sb + (uint32_t)s * GSTAGE;
        const uint32_t aHiB = base;
        const uint32_t aLoB = base + 10240u;
        const uint32_t bHiB = base + 20480u;
        const uint32_t bLoB = base + 30720u;

        #pragma unroll
        for (int kk = 0; kk < 32; kk += 16) {
            uint32_t ah[4][4], al[4][4], bh[4][2], bl[4][2];
            const uint32_t acol = (uint32_t)((kk + ((lane >> 4) << 3)) << 1);
            const uint32_t arow = (uint32_t)(wr * 64 + (lane & 15)) * 80u;
            #pragma unroll
            for (int mt = 0; mt < 4; mt++)
                LDSM_X4(ah[mt][0], ah[mt][1], ah[mt][2], ah[mt][3],
                        aHiB + arow + (uint32_t)(mt * 16) * 80u + acol);
            #pragma unroll
            for (int mt = 0; mt < 4; mt++)
                LDSM_X4(al[mt][0], al[mt][1], al[mt][2], al[mt][3],
                        aLoB + arow + (uint32_t)(mt * 16) * 80u + acol);
            {
                const int g = lane >> 3;
                const int rn = (g >= 2) ? 8 : 0;
                const uint32_t bcol = (uint32_t)((kk + ((g & 1) << 3)) << 1);
                const uint32_t brow = (uint32_t)(wc * 32 + rn + (lane & 7)) * 80u;
                #pragma unroll
                for (int nt2 = 0; nt2 < 2; nt2++)
                    LDSM_X4(bh[nt2*2][0], bh[nt2*2][1], bh[nt2*2+1][0], bh[nt2*2+1][1],
                            bHiB + brow + (uint32_t)(nt2 * 16) * 80u + bcol);
                #pragma unroll
                for (int nt2 = 0; nt2 < 2; nt2++)
                    LDSM_X4(bl[nt2*2][0], bl[nt2*2][1], bl[nt2*2+1][0], bl[nt2*2+1][1],
                            bLoB + brow + (uint32_t)(nt2 * 16) * 80u + bcol);
            }
            #pragma unroll
            for (int mt = 0; mt < 4; mt++)
                #pragma unroll
                for (int nt = 0; nt < 4; nt++)
                    MMA16816(c[mt][nt], ah[mt], bh[nt]);
            #pragma unroll
            for (int mt = 0; mt < 4; mt++)
                #pragma unroll
                for (int nt = 0; nt < 4; nt++)
                    MMA16816(c[mt][nt], ah[mt], bl[nt]);
            #pragma unroll
            for (int mt = 0; mt < 4; mt++)
                #pragma unroll
                for (int nt = 0; nt < 4; nt++)
                    MMA16816(c[mt][nt], al[mt], bh[nt]);
        }
        __syncthreads();
    }

    #pragma unroll
    for (int mt = 0; mt < 4; mt++) {
        #pragma unroll
        for (int nt = 0; nt < 4; nt++) {
            const int r = row0 + wr * 64 + mt * 16 + (lane >> 2);
            const int ccol = col0 + wc * 32 + nt * 8 + ((lane & 3) << 1);
            const float b0 = bias[ccol], b1 = bias[ccol + 1];
            #pragma unroll
            for (int hh = 0; hh < 2; hh++) {
                const int rr = r + hh * 8;
                float v0 = c[mt][nt][hh * 2 + 0] + b0;
                float v1 = c[mt][nt][hh * 2 + 1] + b1;
                if (mode == 1) {
                    v0 = gelu_exact(v0); v1 = gelu_exact(v1);
                    uint32_t wh, wl;
                    split_pack2(v0, v1, wh, wl);
                    *(uint32_t*)(ohi + (size_t)rr * N + ccol) = wh;
                    *(uint32_t*)(olo + (size_t)rr * N + ccol) = wl;
                } else {
                    if (mode == 2) {
                        float2 rv = *(const float2*)(res + (size_t)rr * N + ccol);
                        v0 += rv.x; v1 += rv.y;
                    }
                    *(float2*)(outf + (size_t)rr * N + ccol) = make_float2(v0, v1);
                }
            }
        }
    }
}

// ================= HMMA bf16x3 Flash Attention =================
#define ASTR 72
#define AQ_H 0
#define AQ_L (128 * ASTR)
#define AK_H (2 * 128 * ASTR)
#define AK_L (AK_H + 64 * ASTR)
#define AV_H (AK_L + 64 * ASTR)
#define AV_L (AV_H + 64 * ASTR)
#define ATT2_SMEM ((AV_L + 64 * ASTR) * 2)

__global__ __launch_bounds__(256, 2) void attn_mma(
    const float* __restrict__ qkv,
    unsigned short* __restrict__ ohi, unsigned short* __restrict__ olo)
{
    extern __shared__ unsigned short asmem[];
    const uint32_t sB = smem_u32(asmem);
    const int tid = threadIdx.x;
    const int wid = tid >> 5, lane = tid & 31;
    const int bh = blockIdx.y;
    const int b = bh >> 4, h = bh & 15;
    const int q0 = blockIdx.x * 128;

    const float* qbase = qkv + (size_t)b * 2048 * D_QKV + h * D_HEAD;
    const float* kbase = qbase + D_MODEL;
    const float* vbase = qbase + 2 * D_MODEL;

    // ---- load Q tile (128x64), scale by 1/8, split to hi/lo ----
    {
        const int colb = (tid & 3) * 16;
        #pragma unroll
        for (int i = 0; i < 2; i++) {
            const int row = (tid >> 2) + i * 64;
            const float* src = qbase + (size_t)(q0 + row) * D_QKV + colb;
            #pragma unroll
            for (int u = 0; u < 4; u++) {
                float4 v = *(const float4*)(src + u * 4);
                v.x *= 0.125f; v.y *= 0.125f; v.z *= 0.125f; v.w *= 0.125f;
                uint32_t h01, l01, h23, l23;
                split_pack2(v.x, v.y, h01, l01);
                split_pack2(v.z, v.w, h23, l23);
                const int o = row * ASTR + colb + u * 4;
                *(uint2*)(asmem + AQ_H + o) = make_uint2(h01, h23);
                *(uint2*)(asmem + AQ_L + o) = make_uint2(l01, l23);
            }
        }
    }

    float cO[8][4];
    #pragma unroll
    for (int nt = 0; nt < 8; nt++)
        #pragma unroll
        for (int i = 0; i < 4; i++) cO[nt][i] = 0.f;
    float m2[2] = {-1e30f, -1e30f};
    float l2[2] = {0.f, 0.f};

    const uint32_t qhB = sB + AQ_H * 2, qlB = sB + AQ_L * 2;
    const uint32_t khB = sB + AK_H * 2, klB = sB + AK_L * 2;
    const uint32_t vhB = sB + AV_H * 2, vlB = sB + AV_L * 2;

    for (int kt = 0; kt < 2048; kt += 64) {
        {
            const int row = tid >> 2;
            const int colb = (tid & 3) * 16;
            const float* ks = kbase + (size_t)(kt + row) * D_QKV + colb;
            const float* vs = vbase + (size_t)(kt + row) * D_QKV + colb;
            #pragma unroll
            for (int u = 0; u < 4; u++) {
                float4 kv = *(const float4*)(ks + u * 4);
                uint32_t h01, l01, h23, l23;
                split_pack2(kv.x, kv.y, h01, l01);
                split_pack2(kv.z, kv.w, h23, l23);
                const int o = row * ASTR + colb + u * 4;
                *(uint2*)(asmem + AK_H + o) = make_uint2(h01, h23);
                *(uint2*)(asmem + AK_L + o) = make_uint2(l01, l23);
                float4 vv = *(const float4*)(vs + u * 4);
                split_pack2(vv.x, vv.y, h01, l01);
                split_pack2(vv.z, vv.w, h23, l23);
                *(uint2*)(asmem + AV_H + o) = make_uint2(h01, h23);
                *(uint2*)(asmem + AV_L + o) = make_uint2(l01, l23);
            }
        }
        __syncthreads();

        float cS[8][4];
        #pragma unroll
        for (int nt = 0; nt < 8; nt++)
            #pragma unroll
            for (int i = 0; i < 4; i++) cS[nt][i] = 0.f;

        const uint32_t arow = (uint32_t)(wid * 16 + (lane & 15)) * (ASTR * 2);
        const int g = lane >> 3;
        const int rn = (g >= 2) ? 8 : 0;
        #pragma unroll
        for (int kk = 0; kk < 4; kk++) {
            const uint32_t acol = (uint32_t)((kk * 16 + ((lane >> 4) << 3)) << 1);
            uint32_t ah[4], al[4];
            LDSM_X4(ah[0], ah[1], ah[2], ah[3], qhB + arow + acol);
            LDSM_X4(al[0], al[1], al[2], al[3], qlB + arow + acol);
            const uint32_t bcol = (uint32_t)((kk * 16 + ((g & 1) << 3)) << 1);
            #pragma unroll
            for (int nt2 = 0; nt2 < 4; nt2++) {
                const uint32_t brow = (uint32_t)(nt2 * 16 + rn + (lane & 7)) * (ASTR * 2);
                uint32_t bhf[4], blf[4];
                LDSM_X4(bhf[0], bhf[1], bhf[2], bhf[3], khB + brow + bcol);
                LDSM_X4(blf[0], blf[1], blf[2], blf[3], klB + brow + bcol);
                MMA16816(cS[nt2*2],   ah, bhf);
                MMA16816(cS[nt2*2+1], ah, bhf + 2);
                MMA16816(cS[nt2*2],   ah, blf);
                MMA16816(cS[nt2*2+1], ah, blf + 2);
                MMA16816(cS[nt2*2],   al, bhf);
                MMA16816(cS[nt2*2+1], al, bhf + 2);
            }
        }

        #pragma unroll
        for (int hh = 0; hh < 2; hh++) {
            float mx = cS[0][hh*2];
            #pragma unroll
            for (int nt = 0; nt < 8; nt++) {
                mx = fmaxf(mx, cS[nt][hh*2]);
                mx = fmaxf(mx, cS[nt][hh*2+1]);
            }
            mx = fmaxf(mx, __shfl_xor_sync(0xffffffffu, mx, 1));
            mx = fmaxf(mx, __shfl_xor_sync(0xffffffffu, mx, 2));
            const float mnew = fmaxf(m2[hh], mx);
            const float corr = __expf(m2[hh] - mnew);
            m2[hh] = mnew;
            float sum = 0.f;
            #pragma unroll
            for (int nt = 0; nt < 8; nt++) {
                float p0 = __expf(cS[nt][hh*2]   - mnew);
                float p1 = __expf(cS[nt][hh*2+1] - mnew);
                cS[nt][hh*2] = p0; cS[nt][hh*2+1] = p1;
                sum += p0 + p1;
            }
            sum += __shfl_xor_sync(0xffffffffu, sum, 1);
            sum += __shfl_xor_sync(0xffffffffu, sum, 2);
            l2[hh] = l2[hh] * corr + sum;
            #pragma unroll
            for (int nt = 0; nt < 8; nt++) {
                cO[nt][hh*2]   *= corr;
                cO[nt][hh*2+1] *= corr;
            }
        }

        const int tt = lane >> 3;
        const uint32_t vrow0 = (uint32_t)(((tt & 1) << 3) + (lane & 7)) * (ASTR * 2);
        const uint32_t vcoff = (uint32_t)((tt >> 1) << 3) * 2;
        #pragma unroll
        for (int kk2 = 0; kk2 < 4; kk2++) {
            uint32_t ahi[4], alo[4];
            split_pack2(cS[2*kk2][0],   cS[2*kk2][1],   ahi[0], alo[0]);
            split_pack2(cS[2*kk2][2],   cS[2*kk2][3],   ahi[1], alo[1]);
            split_pack2(cS[2*kk2+1][0], cS[2*kk2+1][1], ahi[2], alo[2]);
            split_pack2(cS[2*kk2+1][2], cS[2*kk2+1][3], ahi[3], alo[3]);
            const uint32_t vrow = vrow0 + (uint32_t)(kk2 * 16) * (ASTR * 2);
            #pragma unroll
            for (int nt2 = 0; nt2 < 4; nt2++) {
                const uint32_t vcol = (uint32_t)(nt2 * 16) * 2 + vcoff;
                uint32_t bvh[4], bvl[4];
                LDSM_X4_T(bvh[0], bvh[1], bvh[2], bvh[3], vhB + vrow + vcol);
                LDSM_X4_T(bvl[0], bvl[1], bvl[2], bvl[3], vlB + vrow + vcol);
                MMA16816(cO[nt2*2],   ahi, bvh);
                MMA16816(cO[nt2*2+1], ahi, bvh + 2);
                MMA16816(cO[nt2*2],   ahi, bvl);
                MMA16816(cO[nt2*2+1], ahi, bvl + 2);
                MMA16816(cO[nt2*2],   alo, bvh);
                MMA16816(cO[nt2*2+1], alo, bvh + 2);
            }
        }
        __syncthreads();
    }

    #pragma unroll
    for (int hh = 0; hh < 2; hh++) {
        const float inv = 1.0f / l2[hh];
        const int row = q0 + wid * 16 + (lane >> 2) + hh * 8;
        const size_t rbase = ((size_t)b * 2048 + row) * D_MODEL + h * D_HEAD + ((lane & 3) << 1);
        #pragma unroll
        for (int nt = 0; nt < 8; nt++) {
            float v0 = cO[nt][hh*2]   * inv;
            float v1 = cO[nt][hh*2+1] * inv;
            uint32_t wh, wl;
            split_pack2(v0, v1, wh, wl);
            *(uint32_t*)(ohi + rbase + nt * 8) = wh;
            *(uint32_t*)(olo + rbase + nt * 8) = wl;
        }
    }
}

// ================= launch =================
extern "C" void kernel_launch(void* const* d_in, const int* in_sizes, int n_in,
                              void* d_out, int out_size)
{
    (void)in_sizes; (void)n_in; (void)out_size;
    const float* x     = (const float*)d_in[0];
    const float* ln1_g = (const float*)d_in[1];
    const float* ln1_b = (const float*)d_in[2];
    const float* w_qkv = (const float*)d_in[3];
    const float* b_qkv = (const float*)d_in[4];
    const float* w_out = (const float*)d_in[5];
    const float* b_out = (const float*)d_in[6];
    const float* ln2_g = (const float*)d_in[7];
    const float* ln2_b = (const float*)d_in[8];
    const float* w1    = (const float*)d_in[9];
    const float* b1    = (const float*)d_in[10];
    const float* w2    = (const float*)d_in[11];
    const float* b2    = (const float*)d_in[12];
    float* out = (float*)d_out;

    float *qkv, *x2;
    unsigned short *lnh, *lnl, *ath, *atl, *h1h, *h1l;
    unsigned short *wqh, *wql, *woh, *wol, *w1h, *w1l, *w2h, *w2l;
    cudaGetSymbolAddress((void**)&qkv, g_qkv);
    cudaGetSymbolAddress((void**)&x2,  g_x2);
    cudaGetSymbolAddress((void**)&lnh, g_ln_hi); cudaGetSymbolAddress((void**)&lnl, g_ln_lo);
    cudaGetSymbolAddress((void**)&ath, g_at_hi); cudaGetSymbolAddress((void**)&atl, g_at_lo);
    cudaGetSymbolAddress((void**)&h1h, g_h1_hi); cudaGetSymbolAddress((void**)&h1l, g_h1_lo);
    cudaGetSymbolAddress((void**)&wqh, g_wqkv_hi); cudaGetSymbolAddress((void**)&wql, g_wqkv_lo);
    cudaGetSymbolAddress((void**)&woh, g_wout_hi); cudaGetSymbolAddress((void**)&wol, g_wout_lo);
    cudaGetSymbolAddress((void**)&w1h, g_w1_hi);   cudaGetSymbolAddress((void**)&w1l, g_w1_lo);
    cudaGetSymbolAddress((void**)&w2h, g_w2_hi);   cudaGetSymbolAddress((void**)&w2l, g_w2_lo);

    cudaFuncSetAttribute(attn_mma, cudaFuncAttributeMaxDynamicSharedMemorySize, ATT2_SMEM);
    cudaFuncSetAttribute(gemm_tc,  cudaFuncAttributeMaxDynamicSharedMemorySize, GT_SMEM);

    dim3 wb(32, 8);
    wconv_kernel<<<dim3(D_QKV / 32, D_MODEL / 32), wb>>>(w_qkv, wqh, wql, D_MODEL, D_QKV);
    wconv_kernel<<<dim3(D_MODEL / 32, D_MODEL / 32), wb>>>(w_out, woh, wol, D_MODEL, D_MODEL);
    wconv_kernel<<<dim3(D_FF / 32, D_MODEL / 32), wb>>>(w1, w1h, w1l, D_MODEL, D_FF);
    wconv_kernel<<<dim3(D_MODEL / 32, D_FF / 32), wb>>>(w2, w2h, w2l, D_FF, D_MODEL);

    ln_kernel<<<M_ROWS, 256>>>(x, ln1_g, ln1_b, lnh, lnl);
    gemm_tc<<<dim3(D_QKV / 128, M_ROWS / 128), 256, GT_SMEM>>>(
        lnh, lnl, wqh, wql, b_qkv, nullptr, qkv, nullptr, nullptr,
        M_ROWS, D_QKV, D_MODEL, 0);
    attn_mma<<<dim3(2048 / 128, 2 * N_HEADS), 256, ATT2_SMEM>>>(qkv, ath, atl);
    gemm_tc<<<dim3(D_MODEL / 128, M_ROWS / 128), 256, GT_SMEM>>>(
        ath, atl, woh, wol, b_out, x, x2, nullptr, nullptr,
        M_ROWS, D_MODEL, D_MODEL, 2);
    ln_kernel<<<M_ROWS, 256>>>(x2, ln2_g, ln2_b, lnh, lnl);
    gemm_tc<<<dim3(D_FF / 128, M_ROWS / 128), 256, GT_SMEM>>>(
        lnh, lnl, w1h, w1l, b1, nullptr, nullptr, h1h, h1l,
        M_ROWS, D_FF, D_MODEL, 1);
    gemm_tc<<<dim3(D_MODEL / 128, M_ROWS / 128), 256, GT_SMEM>>>(
        h1h, h1l, w2h, w2l, b2, x2, out, nullptr, nullptr,
        M_ROWS, D_MODEL, D_FF, 2);
}

// round 8
// speedup vs baseline: 2.7816x; 1.0340x over previous
#include <cuda_runtime.h>
#include <cuda_bf16.h>
#include <math.h>
#include <stdint.h>

// Problem: B=2, S=2048, D=1024, H=16, DH=64
#define M_ROWS 4096
#define D_MODEL 1024
#define D_QKV   3072
#define D_FF    4096
#define N_HEADS 16
#define D_HEAD  64

// ---------------- scratch (device globals; no allocation) ----------------
__device__ float g_x2 [M_ROWS * D_MODEL];
__device__ unsigned short g_qkv_hi[M_ROWS * D_QKV], g_qkv_lo[M_ROWS * D_QKV];
__device__ unsigned short g_ln_hi[M_ROWS * D_MODEL], g_ln_lo[M_ROWS * D_MODEL];
__device__ unsigned short g_at_hi[M_ROWS * D_MODEL], g_at_lo[M_ROWS * D_MODEL];
__device__ unsigned short g_h1_hi[M_ROWS * D_FF],    g_h1_lo[M_ROWS * D_FF];
__device__ unsigned short g_wqkv_hi[D_QKV * D_MODEL], g_wqkv_lo[D_QKV * D_MODEL];
__device__ unsigned short g_wout_hi[D_MODEL * D_MODEL], g_wout_lo[D_MODEL * D_MODEL];
__device__ unsigned short g_w1_hi[D_FF * D_MODEL],   g_w1_lo[D_FF * D_MODEL];
__device__ unsigned short g_w2_hi[D_MODEL * D_FF],   g_w2_lo[D_MODEL * D_FF];

// ---------------- helpers ----------------
__device__ __forceinline__ uint32_t smem_u32(const void* p) {
    uint32_t a;
    asm("{ .reg .u64 t; cvta.to.shared.u64 t, %1; cvt.u32.u64 %0, t; }" : "=r"(a) : "l"(p));
    return a;
}
__device__ __forceinline__ void cp16(uint32_t dst, const void* src) {
    asm volatile("cp.async.cg.shared.global [%0], [%1], 16;" :: "r"(dst), "l"(src));
}
#define CP_COMMIT() asm volatile("cp.async.commit_group;" ::: "memory")
#define CP_WAIT1()  asm volatile("cp.async.wait_group 1;" ::: "memory")
#define CP_WAIT0()  asm volatile("cp.async.wait_group 0;" ::: "memory")

#define LDSM_X4(r0, r1, r2, r3, addr) \
    asm volatile("ldmatrix.sync.aligned.m8n8.x4.shared.b16 {%0,%1,%2,%3}, [%4];" \
        : "=r"(r0), "=r"(r1), "=r"(r2), "=r"(r3) : "r"(addr))

#define LDSM_X4_T(r0, r1, r2, r3, addr) \
    asm volatile("ldmatrix.sync.aligned.m8n8.x4.trans.shared.b16 {%0,%1,%2,%3}, [%4];" \
        : "=r"(r0), "=r"(r1), "=r"(r2), "=r"(r3) : "r"(addr))

#define MMA16816(c, a, b) \
    asm volatile("mma.sync.aligned.m16n8k16.row.col.f32.bf16.bf16.f32 " \
        "{%0,%1,%2,%3}, {%4,%5,%6,%7}, {%8,%9}, {%0,%1,%2,%3};" \
        : "+f"((c)[0]), "+f"((c)[1]), "+f"((c)[2]), "+f"((c)[3]) \
        : "r"((a)[0]), "r"((a)[1]), "r"((a)[2]), "r"((a)[3]), "r"((b)[0]), "r"((b)[1]))

__device__ __forceinline__ float gelu_exact(float v) {
    return 0.5f * v * (1.0f + erff(v * 0.70710678118654752f));
}
__device__ __forceinline__ void split_bf16(float v, unsigned short& hi, unsigned short& lo) {
    __nv_bfloat16 h = __float2bfloat16(v);
    float r = v - __bfloat162float(h);
    hi = __bfloat16_as_ushort(h);
    lo = __bfloat16_as_ushort(__float2bfloat16(r));
}
__device__ __forceinline__ void split_pack2(float x, float y, uint32_t& whi, uint32_t& wlo) {
    unsigned short hx, lx, hy, ly;
    split_bf16(x, hx, lx); split_bf16(y, hy, ly);
    whi = (uint32_t)hx | ((uint32_t)hy << 16);
    wlo = (uint32_t)lx | ((uint32_t)ly << 16);
}

// ================= weight transpose + bf16 hi/lo split =================
__global__ void wconv_kernel(const float* __restrict__ W,
                             unsigned short* __restrict__ Thi,
                             unsigned short* __restrict__ Tlo, int K, int N)
{
    __shared__ float t[32][33];
    int n0 = blockIdx.x * 32, k0 = blockIdx.y * 32;
    int tx = threadIdx.x, ty = threadIdx.y;
    #pragma unroll
    for (int i = 0; i < 32; i += 8)
        t[ty + i][tx] = W[(size_t)(k0 + ty + i) * N + n0 + tx];
    __syncthreads();
    #pragma unroll
    for (int i = 0; i < 32; i += 8) {
        float v = t[tx][ty + i];
        unsigned short h, l;
        split_bf16(v, h, l);
        size_t o = (size_t)(n0 + ty + i) * K + k0 + tx;
        Thi[o] = h; Tlo[o] = l;
    }
}

// ================= LayerNorm (writes bf16 hi/lo) =================
__global__ __launch_bounds__(256) void ln_kernel(
    const float* __restrict__ x, const float* __restrict__ g,
    const float* __restrict__ b,
    unsigned short* __restrict__ yhi, unsigned short* __restrict__ ylo)
{
    int row = blockIdx.x;
    const float* xr = x + (size_t)row * D_MODEL;
    int tid = threadIdx.x;
    float4 v = *(const float4*)(xr + tid * 4);
    float s = v.x + v.y + v.z + v.w;
    float q = v.x*v.x + v.y*v.y + v.z*v.z + v.w*v.w;
    #pragma unroll
    for (int off = 16; off > 0; off >>= 1) {
        s += __shfl_xor_sync(0xffffffffu, s, off);
        q += __shfl_xor_sync(0xffffffffu, q, off);
    }
    __shared__ float sh_s[8], sh_q[8];
    int w = tid >> 5, lane = tid & 31;
    if (lane == 0) { sh_s[w] = s; sh_q[w] = q; }
    __syncthreads();
    if (tid == 0) {
        float ts = 0.f, tq = 0.f;
        #pragma unroll
        for (int i = 0; i < 8; i++) { ts += sh_s[i]; tq += sh_q[i]; }
        sh_s[0] = ts; sh_q[0] = tq;
    }
    __syncthreads();
    float mean = sh_s[0] * (1.f / D_MODEL);
    float var  = sh_q[0] * (1.f / D_MODEL) - mean * mean;
    float rstd = rsqrtf(var + 1e-5f);
    float4 gv = *(const float4*)(g + tid * 4);
    float4 bv = *(const float4*)(b + tid * 4);
    float o0 = (v.x - mean) * rstd * gv.x + bv.x;
    float o1 = (v.y - mean) * rstd * gv.y + bv.y;
    float o2 = (v.z - mean) * rstd * gv.z + bv.z;
    float o3 = (v.w - mean) * rstd * gv.w + bv.w;
    uint32_t h01, l01, h23, l23;
    split_pack2(o0, o1, h01, l01);
    split_pack2(o2, o3, h23, l23);
    size_t off = (size_t)row * D_MODEL + tid * 4;
    *(uint2*)(yhi + off) = make_uint2(h01, h23);
    *(uint2*)(ylo + off) = make_uint2(l01, l23);
}

// ================= HMMA bf16x3 GEMM =================
// mode 0: outf = C+bias ; 1: (ohi,olo)=split(gelu(C+bias)) ; 2: outf=C+bias+res ;
// mode 3: (ohi,olo)=split(C+bias)
#define GSTAGE 40960
#define GT_SMEM (2 * GSTAGE)

__global__ __launch_bounds__(256, 2) void gemm_tc(
    const unsigned short* __restrict__ Ahi, const unsigned short* __restrict__ Alo,
    const unsigned short* __restrict__ Bhi, const unsigned short* __restrict__ Blo,
    const float* __restrict__ bias, const float* __restrict__ res,
    float* __restrict__ outf,
    unsigned short* __restrict__ ohi, unsigned short* __restrict__ olo,
    int M, int N, int K, int mode)
{
    extern __shared__ char smem[];
    const uint32_t sb = smem_u32(smem);
    const int tid = threadIdx.x;
    const int wid = tid >> 5, lane = tid & 31;
    const int wr = wid >> 2, wc = wid & 3;
    const int row0 = blockIdx.y * 128, col0 = blockIdx.x * 128;

    const int lr = tid >> 2;
    const int lj = tid & 3;

    float c[4][4][4];
    #pragma unroll
    for (int mt = 0; mt < 4; mt++)
        #pragma unroll
        for (int nt = 0; nt < 4; nt++)
            #pragma unroll
            for (int i = 0; i < 4; i++) c[mt][nt][i] = 0.f;

    const int nch = K >> 5;

    auto issue = [&](int cc, int s) {
        const int k0 = cc * 32;
        const uint32_t base = sb + (uint32_t)s * GSTAGE;
        const uint32_t ro = (uint32_t)lr * 80u + (uint32_t)lj * 16u;
        const size_t asrc = (size_t)(row0 + lr) * K + k0 + lj * 8;
        const size_t bsrc = (size_t)(col0 + lr) * K + k0 + lj * 8;
        const size_t step = (size_t)64 * K;
        cp16(base +          ro,            Ahi + asrc);
        cp16(base +          ro + 64 * 80u, Ahi + asrc + step);
        cp16(base + 10240u + ro,            Alo + asrc);
        cp16(base + 10240u + ro + 64 * 80u, Alo + asrc + step);
        cp16(base + 20480u + ro,            Bhi + bsrc);
        cp16(base + 20480u + ro + 64 * 80u, Bhi + bsrc + step);
        cp16(base + 30720u + ro,            Blo + bsrc);
        cp16(base + 30720u + ro + 64 * 80u, Blo + bsrc + step);
    };

    issue(0, 0);
    CP_COMMIT();

    for (int cc = 0; cc < nch; cc++) {
        const int s = cc & 1;
        if (cc + 1 < nch) { issue(cc + 1, s ^ 1); CP_COMMIT(); CP_WAIT1(); }
        else              { CP_WAIT0(); }
        __syncthreads();

        const uint32_t base = sb + (uint32_t)s * GSTAGE;
        const uint32_t aHiB = base;
        const uint32_t aLoB = base + 10240u;
        const uint32_t bHiB = base + 20480u;
        const uint32_t bLoB = base + 30720u;

        #pragma unroll
        for (int kk = 0; kk < 32; kk += 16) {
            uint32_t ah[4][4], al[4][4], bh[4][2], bl[4][2];
            const uint32_t acol = (uint32_t)((kk + ((lane >> 4) << 3)) << 1);
            const uint32_t arow = (uint32_t)(wr * 64 + (lane & 15)) * 80u;
            #pragma unroll
            for (int mt = 0; mt < 4; mt++)
                LDSM_X4(ah[mt][0], ah[mt][1], ah[mt][2], ah[mt][3],
                        aHiB + arow + (uint32_t)(mt * 16) * 80u + acol);
            #pragma unroll
            for (int mt = 0; mt < 4; mt++)
                LDSM_X4(al[mt][0], al[mt][1], al[mt][2], al[mt][3],
                        aLoB + arow + (uint32_t)(mt * 16) * 80u + acol);
            {
                const int g = lane >> 3;
                const int rn = (g >= 2) ? 8 : 0;
                const uint32_t bcol = (uint32_t)((kk + ((g & 1) << 3)) << 1);
                const uint32_t brow = (uint32_t)(wc * 32 + rn + (lane & 7)) * 80u;
                #pragma unroll
                for (int nt2 = 0; nt2 < 2; nt2++)
                    LDSM_X4(bh[nt2*2][0], bh[nt2*2][1], bh[nt2*2+1][0], bh[nt2*2+1][1],
                            bHiB + brow + (uint32_t)(nt2 * 16) * 80u + bcol);
                #pragma unroll
                for (int nt2 = 0; nt2 < 2; nt2++)
                    LDSM_X4(bl[nt2*2][0], bl[nt2*2][1], bl[nt2*2+1][0], bl[nt2*2+1][1],
                            bLoB + brow + (uint32_t)(nt2 * 16) * 80u + bcol);
            }
            #pragma unroll
            for (int mt = 0; mt < 4; mt++)
                #pragma unroll
                for (int nt = 0; nt < 4; nt++)
                    MMA16816(c[mt][nt], ah[mt], bh[nt]);
            #pragma unroll
            for (int mt = 0; mt < 4; mt++)
                #pragma unroll
                for (int nt = 0; nt < 4; nt++)
                    MMA16816(c[mt][nt], ah[mt], bl[nt]);
            #pragma unroll
            for (int mt = 0; mt < 4; mt++)
                #pragma unroll
                for (int nt = 0; nt < 4; nt++)
                    MMA16816(c[mt][nt], al[mt], bh[nt]);
        }
        __syncthreads();
    }

    #pragma unroll
    for (int mt = 0; mt < 4; mt++) {
        #pragma unroll
        for (int nt = 0; nt < 4; nt++) {
            const int r = row0 + wr * 64 + mt * 16 + (lane >> 2);
            const int ccol = col0 + wc * 32 + nt * 8 + ((lane & 3) << 1);
            const float b0 = bias[ccol], b1 = bias[ccol + 1];
            #pragma unroll
            for (int hh = 0; hh < 2; hh++) {
                const int rr = r + hh * 8;
                float v0 = c[mt][nt][hh * 2 + 0] + b0;
                float v1 = c[mt][nt][hh * 2 + 1] + b1;
                if (mode == 1 || mode == 3) {
                    if (mode == 1) { v0 = gelu_exact(v0); v1 = gelu_exact(v1); }
                    uint32_t wh, wl;
                    split_pack2(v0, v1, wh, wl);
                    *(uint32_t*)(ohi + (size_t)rr * N + ccol) = wh;
                    *(uint32_t*)(olo + (size_t)rr * N + ccol) = wl;
                } else {
                    if (mode == 2) {
                        float2 rv = *(const float2*)(res + (size_t)rr * N + ccol);
                        v0 += rv.x; v1 += rv.y;
                    }
                    *(float2*)(outf + (size_t)rr * N + ccol) = make_float2(v0, v1);
                }
            }
        }
    }
}

// ================= HMMA bf16x3 Flash Attention (cp.async K/V pipeline) =================
// QKV arrives pre-split (hi/lo bf16). K/V tiles double-buffered via cp.async.
// SMEM (ushort idx): Q hi[128*72], Q lo[128*72], 2 stages of {Khi,Klo,Vhi,Vlo}[64*72].
#define ASTR 72
#define AQ_H 0
#define AQ_L (128 * ASTR)
#define KV_BASE (2 * 128 * ASTR)
#define KV_STAGE (4 * 64 * ASTR)
#define KV_MAT (64 * ASTR)
#define ATT2_SMEM ((KV_BASE + 2 * KV_STAGE) * 2)   // 110592 bytes

__global__ __launch_bounds__(256, 2) void attn_mma(
    const unsigned short* __restrict__ qh, const unsigned short* __restrict__ ql,
    unsigned short* __restrict__ ohi, unsigned short* __restrict__ olo)
{
    extern __shared__ unsigned short asmem[];
    const uint32_t sB = smem_u32(asmem);
    const int tid = threadIdx.x;
    const int wid = tid >> 5, lane = tid & 31;
    const int bh = blockIdx.y;
    const int b = bh >> 4, h = bh & 15;
    const int q0 = blockIdx.x * 128;

    // ---- load Q tile (128x64 hi/lo) — plain copies, once per block ----
    {
        const int row = tid >> 2;
        const int jj = tid & 3;
        #pragma unroll
        for (int i = 0; i < 2; i++) {
            const size_t src = (size_t)(b * 2048 + q0 + row + i * 64) * D_QKV + h * D_HEAD + jj * 16;
            const int dst = (row + i * 64) * ASTR + jj * 16;
            *(uint4*)(asmem + AQ_H + dst)     = *(const uint4*)(qh + src);
            *(uint4*)(asmem + AQ_H + dst + 8) = *(const uint4*)(qh + src + 8);
            *(uint4*)(asmem + AQ_L + dst)     = *(const uint4*)(ql + src);
            *(uint4*)(asmem + AQ_L + dst + 8) = *(const uint4*)(ql + src + 8);
        }
    }

    // cp.async K/V tile loader
    auto issueKV = [&](int kt, int s) {
        const int row = tid >> 2;
        const int jj = tid & 3;
        const uint32_t dst = sB + (uint32_t)(KV_BASE + s * KV_STAGE + row * ASTR + jj * 16) * 2;
        const size_t srow = (size_t)(b * 2048 + kt + row) * D_QKV + h * D_HEAD + jj * 16;
        const unsigned short* khp = qh + srow + D_MODEL;
        const unsigned short* klp = ql + srow + D_MODEL;
        const unsigned short* vhp = qh + srow + 2 * D_MODEL;
        const unsigned short* vlp = ql + srow + 2 * D_MODEL;
        cp16(dst,                       khp);  cp16(dst + 16,                       khp + 8);
        cp16(dst + KV_MAT * 2,          klp);  cp16(dst + KV_MAT * 2 + 16,          klp + 8);
        cp16(dst + 2 * KV_MAT * 2,      vhp);  cp16(dst + 2 * KV_MAT * 2 + 16,      vhp + 8);
        cp16(dst + 3 * KV_MAT * 2,      vlp);  cp16(dst + 3 * KV_MAT * 2 + 16,      vlp + 8);
    };

    float cO[8][4];
    #pragma unroll
    for (int nt = 0; nt < 8; nt++)
        #pragma unroll
        for (int i = 0; i < 4; i++) cO[nt][i] = 0.f;
    float m2[2] = {-1e30f, -1e30f};
    float l2[2] = {0.f, 0.f};

    const uint32_t qhB = sB + AQ_H * 2, qlB = sB + AQ_L * 2;

    issueKV(0, 0);
    CP_COMMIT();

    for (int it = 0; it < 32; it++) {
        const int s = it & 1;
        if (it + 1 < 32) { issueKV((it + 1) * 64, s ^ 1); CP_COMMIT(); CP_WAIT1(); }
        else             { CP_WAIT0(); }
        __syncthreads();

        const uint32_t khB = sB + (uint32_t)(KV_BASE + s * KV_STAGE) * 2;
        const uint32_t klB = khB + KV_MAT * 2;
        const uint32_t vhB = khB + 2 * KV_MAT * 2;
        const uint32_t vlB = khB + 3 * KV_MAT * 2;

        // ---- S = Q K^T (bf16x3) ----
        float cS[8][4];
        #pragma unroll
        for (int nt = 0; nt < 8; nt++)
            #pragma unroll
            for (int i = 0; i < 4; i++) cS[nt][i] = 0.f;

        const uint32_t arow = (uint32_t)(wid * 16 + (lane & 15)) * (ASTR * 2);
        const int g = lane >> 3;
        const int rn = (g >= 2) ? 8 : 0;
        #pragma unroll
        for (int kk = 0; kk < 4; kk++) {
            const uint32_t acol = (uint32_t)((kk * 16 + ((lane >> 4) << 3)) << 1);
            uint32_t ah[4], al[4];
            LDSM_X4(ah[0], ah[1], ah[2], ah[3], qhB + arow + acol);
            LDSM_X4(al[0], al[1], al[2], al[3], qlB + arow + acol);
            const uint32_t bcol = (uint32_t)((kk * 16 + ((g & 1) << 3)) << 1);
            #pragma unroll
            for (int nt2 = 0; nt2 < 4; nt2++) {
                const uint32_t brow = (uint32_t)(nt2 * 16 + rn + (lane & 7)) * (ASTR * 2);
                uint32_t bhf[4], blf[4];
                LDSM_X4(bhf[0], bhf[1], bhf[2], bhf[3], khB + brow + bcol);
                LDSM_X4(blf[0], blf[1], blf[2], blf[3], klB + brow + bcol);
                MMA16816(cS[nt2*2],   ah, bhf);
                MMA16816(cS[nt2*2+1], ah, bhf + 2);
                MMA16816(cS[nt2*2],   ah, blf);
                MMA16816(cS[nt2*2+1], ah, blf + 2);
                MMA16816(cS[nt2*2],   al, bhf);
                MMA16816(cS[nt2*2+1], al, bhf + 2);
            }
        }
        // apply 1/sqrt(DH) scale (exact power of 2)
        #pragma unroll
        for (int nt = 0; nt < 8; nt++)
            #pragma unroll
            for (int i = 0; i < 4; i++) cS[nt][i] *= 0.125f;

        // ---- online softmax ----
        #pragma unroll
        for (int hh = 0; hh < 2; hh++) {
            float mx = cS[0][hh*2];
            #pragma unroll
            for (int nt = 0; nt < 8; nt++) {
                mx = fmaxf(mx, cS[nt][hh*2]);
                mx = fmaxf(mx, cS[nt][hh*2+1]);
            }
            mx = fmaxf(mx, __shfl_xor_sync(0xffffffffu, mx, 1));
            mx = fmaxf(mx, __shfl_xor_sync(0xffffffffu, mx, 2));
            const float mnew = fmaxf(m2[hh], mx);
            const float corr = __expf(m2[hh] - mnew);
            m2[hh] = mnew;
            float sum = 0.f;
            #pragma unroll
            for (int nt = 0; nt < 8; nt++) {
                float p0 = __expf(cS[nt][hh*2]   - mnew);
                float p1 = __expf(cS[nt][hh*2+1] - mnew);
                cS[nt][hh*2] = p0; cS[nt][hh*2+1] = p1;
                sum += p0 + p1;
            }
            sum += __shfl_xor_sync(0xffffffffu, sum, 1);
            sum += __shfl_xor_sync(0xffffffffu, sum, 2);
            l2[hh] = l2[hh] * corr + sum;
            #pragma unroll
            for (int nt = 0; nt < 8; nt++) {
                cO[nt][hh*2]   *= corr;
                cO[nt][hh*2+1] *= corr;
            }
        }

        // ---- O += P V (bf16x3) ----
        const int tt = lane >> 3;
        const uint32_t vrow0 = (uint32_t)(((tt & 1) << 3) + (lane & 7)) * (ASTR * 2);
        const uint32_t vcoff = (uint32_t)((tt >> 1) << 3) * 2;
        #pragma unroll
        for (int kk2 = 0; kk2 < 4; kk2++) {
            uint32_t ahi[4], alo[4];
            split_pack2(cS[2*kk2][0],   cS[2*kk2][1],   ahi[0], alo[0]);
            split_pack2(cS[2*kk2][2],   cS[2*kk2][3],   ahi[1], alo[1]);
            split_pack2(cS[2*kk2+1][0], cS[2*kk2+1][1], ahi[2], alo[2]);
            split_pack2(cS[2*kk2+1][2], cS[2*kk2+1][3], ahi[3], alo[3]);
            const uint32_t vrow = vrow0 + (uint32_t)(kk2 * 16) * (ASTR * 2);
            #pragma unroll
            for (int nt2 = 0; nt2 < 4; nt2++) {
                const uint32_t vcol = (uint32_t)(nt2 * 16) * 2 + vcoff;
                uint32_t bvh[4], bvl[4];
                LDSM_X4_T(bvh[0], bvh[1], bvh[2], bvh[3], vhB + vrow + vcol);
                LDSM_X4_T(bvl[0], bvl[1], bvl[2], bvl[3], vlB + vrow + vcol);
                MMA16816(cO[nt2*2],   ahi, bvh);
                MMA16816(cO[nt2*2+1], ahi, bvh + 2);
                MMA16816(cO[nt2*2],   ahi, bvl);
                MMA16816(cO[nt2*2+1], ahi, bvl + 2);
                MMA16816(cO[nt2*2],   alo, bvh);
                MMA16816(cO[nt2*2+1], alo, bvh + 2);
            }
        }
        __syncthreads();
    }

    // ---- epilogue ----
    #pragma unroll
    for (int hh = 0; hh < 2; hh++) {
        const float inv = 1.0f / l2[hh];
        const int row = q0 + wid * 16 + (lane >> 2) + hh * 8;
        const size_t rbase = ((size_t)b * 2048 + row) * D_MODEL + h * D_HEAD + ((lane & 3) << 1);
        #pragma unroll
        for (int nt = 0; nt < 8; nt++) {
            float v0 = cO[nt][hh*2]   * inv;
            float v1 = cO[nt][hh*2+1] * inv;
            uint32_t wh, wl;
            split_pack2(v0, v1, wh, wl);
            *(uint32_t*)(ohi + rbase + nt * 8) = wh;
            *(uint32_t*)(olo + rbase + nt * 8) = wl;
        }
    }
}

// ================= launch =================
extern "C" void kernel_launch(void* const* d_in, const int* in_sizes, int n_in,
                              void* d_out, int out_size)
{
    (void)in_sizes; (void)n_in; (void)out_size;
    const float* x     = (const float*)d_in[0];
    const float* ln1_g = (const float*)d_in[1];
    const float* ln1_b = (const float*)d_in[2];
    const float* w_qkv = (const float*)d_in[3];
    const float* b_qkv = (const float*)d_in[4];
    const float* w_out = (const float*)d_in[5];
    const float* b_out = (const float*)d_in[6];
    const float* ln2_g = (const float*)d_in[7];
    const float* ln2_b = (const float*)d_in[8];
    const float* w1    = (const float*)d_in[9];
    const float* b1    = (const float*)d_in[10];
    const float* w2    = (const float*)d_in[11];
    const float* b2    = (const float*)d_in[12];
    float* out = (float*)d_out;

    float *x2;
    unsigned short *qvh, *qvl, *lnh, *lnl, *ath, *atl, *h1h, *h1l;
    unsigned short *wqh, *wql, *woh, *wol, *w1h, *w1l, *w2h, *w2l;
    cudaGetSymbolAddress((void**)&x2,  g_x2);
    cudaGetSymbolAddress((void**)&qvh, g_qkv_hi); cudaGetSymbolAddress((void**)&qvl, g_qkv_lo);
    cudaGetSymbolAddress((void**)&lnh, g_ln_hi); cudaGetSymbolAddress((void**)&lnl, g_ln_lo);
    cudaGetSymbolAddress((void**)&ath, g_at_hi); cudaGetSymbolAddress((void**)&atl, g_at_lo);
    cudaGetSymbolAddress((void**)&h1h, g_h1_hi); cudaGetSymbolAddress((void**)&h1l, g_h1_lo);
    cudaGetSymbolAddress((void**)&wqh, g_wqkv_hi); cudaGetSymbolAddress((void**)&wql, g_wqkv_lo);
    cudaGetSymbolAddress((void**)&woh, g_wout_hi); cudaGetSymbolAddress((void**)&wol, g_wout_lo);
    cudaGetSymbolAddress((void**)&w1h, g_w1_hi);   cudaGetSymbolAddress((void**)&w1l, g_w1_lo);
    cudaGetSymbolAddress((void**)&w2h, g_w2_hi);   cudaGetSymbolAddress((void**)&w2l, g_w2_lo);

    cudaFuncSetAttribute(attn_mma, cudaFuncAttributeMaxDynamicSharedMemorySize, ATT2_SMEM);
    cudaFuncSetAttribute(gemm_tc,  cudaFuncAttributeMaxDynamicSharedMemorySize, GT_SMEM);

    dim3 wb(32, 8);
    wconv_kernel<<<dim3(D_QKV / 32, D_MODEL / 32), wb>>>(w_qkv, wqh, wql, D_MODEL, D_QKV);
    wconv_kernel<<<dim3(D_MODEL / 32, D_MODEL / 32), wb>>>(w_out, woh, wol, D_MODEL, D_MODEL);
    wconv_kernel<<<dim3(D_FF / 32, D_MODEL / 32), wb>>>(w1, w1h, w1l, D_MODEL, D_FF);
    wconv_kernel<<<dim3(D_MODEL / 32, D_FF / 32), wb>>>(w2, w2h, w2l, D_FF, D_MODEL);

    ln_kernel<<<M_ROWS, 256>>>(x, ln1_g, ln1_b, lnh, lnl);
    // qkv (hi/lo split output, mode 3)
    gemm_tc<<<dim3(D_QKV / 128, M_ROWS / 128), 256, GT_SMEM>>>(
        lnh, lnl, wqh, wql, b_qkv, nullptr, nullptr, qvh, qvl,
        M_ROWS, D_QKV, D_MODEL, 3);
    attn_mma<<<dim3(2048 / 128, 2 * N_HEADS), 256, ATT2_SMEM>>>(qvh, qvl, ath, atl);
    gemm_tc<<<dim3(D_MODEL / 128, M_ROWS / 128), 256, GT_SMEM>>>(
        ath, atl, woh, wol, b_out, x, x2, nullptr, nullptr,
        M_ROWS, D_MODEL, D_MODEL, 2);
    ln_kernel<<<M_ROWS, 256>>>(x2, ln2_g, ln2_b, lnh, lnl);
    gemm_tc<<<dim3(D_FF / 128, M_ROWS / 128), 256, GT_SMEM>>>(
        lnh, lnl, w1h, w1l, b1, nullptr, nullptr, h1h, h1l,
        M_ROWS, D_FF, D_MODEL, 1);
    gemm_tc<<<dim3(D_MODEL / 128, M_ROWS / 128), 256, GT_SMEM>>>(
        h1h, h1l, w2h, w2l, b2, x2, out, nullptr, nullptr,
        M_ROWS, D_MODEL, D_FF, 2);
}

// round 9
// speedup vs baseline: 3.8354x; 1.3789x over previous
#include <cuda_runtime.h>
#include <cuda_fp16.h>
#include <math.h>
#include <stdint.h>

// Problem: B=2, S=2048, D=1024, H=16, DH=64
#define M_ROWS 4096
#define D_MODEL 1024
#define D_QKV   3072
#define D_FF    4096
#define N_HEADS 16
#define D_HEAD  64

// ---------------- scratch (device globals; no allocation) ----------------
__device__ float g_x2 [M_ROWS * D_MODEL];
__device__ unsigned short g_qkv_hi[M_ROWS * D_QKV], g_qkv_lo[M_ROWS * D_QKV];
__device__ unsigned short g_ln_hi[M_ROWS * D_MODEL], g_ln_lo[M_ROWS * D_MODEL];
__device__ unsigned short g_at_hi[M_ROWS * D_MODEL], g_at_lo[M_ROWS * D_MODEL];
__device__ unsigned short g_h1_hi[M_ROWS * D_FF],    g_h1_lo[M_ROWS * D_FF];
// transposed weights [N,K] fp16 (hi only — 2-term scheme)
__device__ unsigned short g_wqkv_h[D_QKV * D_MODEL];
__device__ unsigned short g_wout_h[D_MODEL * D_MODEL];
__device__ unsigned short g_w1_h[D_FF * D_MODEL];
__device__ unsigned short g_w2_h[D_MODEL * D_FF];

// ---------------- helpers ----------------
__device__ __forceinline__ uint32_t smem_u32(const void* p) {
    uint32_t a;
    asm("{ .reg .u64 t; cvta.to.shared.u64 t, %1; cvt.u32.u64 %0, t; }" : "=r"(a) : "l"(p));
    return a;
}
__device__ __forceinline__ void cp16(uint32_t dst, const void* src) {
    asm volatile("cp.async.cg.shared.global [%0], [%1], 16;" :: "r"(dst), "l"(src));
}
#define CP_COMMIT() asm volatile("cp.async.commit_group;" ::: "memory")
#define CP_WAIT1()  asm volatile("cp.async.wait_group 1;" ::: "memory")
#define CP_WAIT0()  asm volatile("cp.async.wait_group 0;" ::: "memory")

#define LDSM_X4(r0, r1, r2, r3, addr) \
    asm volatile("ldmatrix.sync.aligned.m8n8.x4.shared.b16 {%0,%1,%2,%3}, [%4];" \
        : "=r"(r0), "=r"(r1), "=r"(r2), "=r"(r3) : "r"(addr))

#define LDSM_X4_T(r0, r1, r2, r3, addr) \
    asm volatile("ldmatrix.sync.aligned.m8n8.x4.trans.shared.b16 {%0,%1,%2,%3}, [%4];" \
        : "=r"(r0), "=r"(r1), "=r"(r2), "=r"(r3) : "r"(addr))

#define MMA16816(c, a, b) \
    asm volatile("mma.sync.aligned.m16n8k16.row.col.f32.f16.f16.f32 " \
        "{%0,%1,%2,%3}, {%4,%5,%6,%7}, {%8,%9}, {%0,%1,%2,%3};" \
        : "+f"((c)[0]), "+f"((c)[1]), "+f"((c)[2]), "+f"((c)[3]) \
        : "r"((a)[0]), "r"((a)[1]), "r"((a)[2]), "r"((a)[3]), "r"((b)[0]), "r"((b)[1]))

__device__ __forceinline__ float gelu_exact(float v) {
    return 0.5f * v * (1.0f + erff(v * 0.70710678118654752f));
}
__device__ __forceinline__ void split_f16(float v, unsigned short& hi, unsigned short& lo) {
    __half h = __float2half_rn(v);
    float r = v - __half2float(h);
    hi = __half_as_ushort(h);
    lo = __half_as_ushort(__float2half_rn(r));
}
__device__ __forceinline__ void split_pack2(float x, float y, uint32_t& whi, uint32_t& wlo) {
    unsigned short hx, lx, hy, ly;
    split_f16(x, hx, lx); split_f16(y, hy, ly);
    whi = (uint32_t)hx | ((uint32_t)hy << 16);
    wlo = (uint32_t)lx | ((uint32_t)ly << 16);
}

// ================= weight transpose + fp16 round =================
__global__ void wconv_kernel(const float* __restrict__ W,
                             unsigned short* __restrict__ Th, int K, int N)
{
    __shared__ float t[32][33];
    int n0 = blockIdx.x * 32, k0 = blockIdx.y * 32;
    int tx = threadIdx.x, ty = threadIdx.y;
    #pragma unroll
    for (int i = 0; i < 32; i += 8)
        t[ty + i][tx] = W[(size_t)(k0 + ty + i) * N + n0 + tx];
    __syncthreads();
    #pragma unroll
    for (int i = 0; i < 32; i += 8) {
        float v = t[tx][ty + i];
        Th[(size_t)(n0 + ty + i) * K + k0 + tx] =
            __half_as_ushort(__float2half_rn(v));
    }
}

// ================= LayerNorm (writes fp16 hi/lo) =================
__global__ __launch_bounds__(256) void ln_kernel(
    const float* __restrict__ x, const float* __restrict__ g,
    const float* __restrict__ b,
    unsigned short* __restrict__ yhi, unsigned short* __restrict__ ylo)
{
    int row = blockIdx.x;
    const float* xr = x + (size_t)row * D_MODEL;
    int tid = threadIdx.x;
    float4 v = *(const float4*)(xr + tid * 4);
    float s = v.x + v.y + v.z + v.w;
    float q = v.x*v.x + v.y*v.y + v.z*v.z + v.w*v.w;
    #pragma unroll
    for (int off = 16; off > 0; off >>= 1) {
        s += __shfl_xor_sync(0xffffffffu, s, off);
        q += __shfl_xor_sync(0xffffffffu, q, off);
    }
    __shared__ float sh_s[8], sh_q[8];
    int w = tid >> 5, lane = tid & 31;
    if (lane == 0) { sh_s[w] = s; sh_q[w] = q; }
    __syncthreads();
    if (tid == 0) {
        float ts = 0.f, tq = 0.f;
        #pragma unroll
        for (int i = 0; i < 8; i++) { ts += sh_s[i]; tq += sh_q[i]; }
        sh_s[0] = ts; sh_q[0] = tq;
    }
    __syncthreads();
    float mean = sh_s[0] * (1.f / D_MODEL);
    float var  = sh_q[0] * (1.f / D_MODEL) - mean * mean;
    float rstd = rsqrtf(var + 1e-5f);
    float4 gv = *(const float4*)(g + tid * 4);
    float4 bv = *(const float4*)(b + tid * 4);
    float o0 = (v.x - mean) * rstd * gv.x + bv.x;
    float o1 = (v.y - mean) * rstd * gv.y + bv.y;
    float o2 = (v.z - mean) * rstd * gv.z + bv.z;
    float o3 = (v.w - mean) * rstd * gv.w + bv.w;
    uint32_t h01, l01, h23, l23;
    split_pack2(o0, o1, h01, l01);
    split_pack2(o2, o3, h23, l23);
    size_t off = (size_t)row * D_MODEL + tid * 4;
    *(uint2*)(yhi + off) = make_uint2(h01, h23);
    *(uint2*)(ylo + off) = make_uint2(l01, l23);
}

// ================= HMMA fp16x2 GEMM =================
// C = (Ahi+Alo) @ Wh. mode 0: outf=C+bias ; 1: split(gelu(C+bias)) ;
// 2: outf=C+bias+res ; 3: split(C+bias)
// SMEM per stage: Ahi, Alo, Bh — 3 x (128 rows x 80 B) = 30720 B. Double buffered.
#define GSTAGE 30720
#define GT_SMEM (2 * GSTAGE)

__global__ __launch_bounds__(256, 2) void gemm_tc(
    const unsigned short* __restrict__ Ahi, const unsigned short* __restrict__ Alo,
    const unsigned short* __restrict__ Bh,
    const float* __restrict__ bias, const float* __restrict__ res,
    float* __restrict__ outf,
    unsigned short* __restrict__ ohi, unsigned short* __restrict__ olo,
    int M, int N, int K, int mode)
{
    extern __shared__ char smem[];
    const uint32_t sb = smem_u32(smem);
    const int tid = threadIdx.x;
    const int wid = tid >> 5, lane = tid & 31;
    const int wr = wid >> 2, wc = wid & 3;
    const int row0 = blockIdx.y * 128, col0 = blockIdx.x * 128;

    const int lr = tid >> 2;
    const int lj = tid & 3;

    float c[4][4][4];
    #pragma unroll
    for (int mt = 0; mt < 4; mt++)
        #pragma unroll
        for (int nt = 0; nt < 4; nt++)
            #pragma unroll
            for (int i = 0; i < 4; i++) c[mt][nt][i] = 0.f;

    const int nch = K >> 5;

    auto issue = [&](int cc, int s) {
        const int k0 = cc * 32;
        const uint32_t base = sb + (uint32_t)s * GSTAGE;
        const uint32_t ro = (uint32_t)lr * 80u + (uint32_t)lj * 16u;
        const size_t asrc = (size_t)(row0 + lr) * K + k0 + lj * 8;
        const size_t bsrc = (size_t)(col0 + lr) * K + k0 + lj * 8;
        const size_t step = (size_t)64 * K;
        cp16(base +          ro,            Ahi + asrc);
        cp16(base +          ro + 64 * 80u, Ahi + asrc + step);
        cp16(base + 10240u + ro,            Alo + asrc);
        cp16(base + 10240u + ro + 64 * 80u, Alo + asrc + step);
        cp16(base + 20480u + ro,            Bh + bsrc);
        cp16(base + 20480u + ro + 64 * 80u, Bh + bsrc + step);
    };

    issue(0, 0);
    CP_COMMIT();

    for (int cc = 0; cc < nch; cc++) {
        const int s = cc & 1;
        if (cc + 1 < nch) { issue(cc + 1, s ^ 1); CP_COMMIT(); CP_WAIT1(); }
        else              { CP_WAIT0(); }
        __syncthreads();

        const uint32_t base = sb + (uint32_t)s * GSTAGE;
        const uint32_t aHiB = base;
        const uint32_t aLoB = base + 10240u;
        const uint32_t bHB  = base + 20480u;

        #pragma unroll
        for (int kk = 0; kk < 32; kk += 16) {
            uint32_t ah[4][4], al[4][4], bh[4][2];
            const uint32_t acol = (uint32_t)((kk + ((lane >> 4) << 3)) << 1);
            const uint32_t arow = (uint32_t)(wr * 64 + (lane & 15)) * 80u;
            #pragma unroll
            for (int mt = 0; mt < 4; mt++)
                LDSM_X4(ah[mt][0], ah[mt][1], ah[mt][2], ah[mt][3],
                        aHiB + arow + (uint32_t)(mt * 16) * 80u + acol);
            #pragma unroll
            for (int mt = 0; mt < 4; mt++)
                LDSM_X4(al[mt][0], al[mt][1], al[mt][2], al[mt][3],
                        aLoB + arow + (uint32_t)(mt * 16) * 80u + acol);
            {
                const int g = lane >> 3;
                const int rn = (g >= 2) ? 8 : 0;
                const uint32_t bcol = (uint32_t)((kk + ((g & 1) << 3)) << 1);
                const uint32_t brow = (uint32_t)(wc * 32 + rn + (lane & 7)) * 80u;
                #pragma unroll
                for (int nt2 = 0; nt2 < 2; nt2++)
                    LDSM_X4(bh[nt2*2][0], bh[nt2*2][1], bh[nt2*2+1][0], bh[nt2*2+1][1],
                            bHB + brow + (uint32_t)(nt2 * 16) * 80u + bcol);
            }
            #pragma unroll
            for (int mt = 0; mt < 4; mt++)
                #pragma unroll
                for (int nt = 0; nt < 4; nt++)
                    MMA16816(c[mt][nt], ah[mt], bh[nt]);
            #pragma unroll
            for (int mt = 0; mt < 4; mt++)
                #pragma unroll
                for (int nt = 0; nt < 4; nt++)
                    MMA16816(c[mt][nt], al[mt], bh[nt]);
        }
        __syncthreads();
    }

    #pragma unroll
    for (int mt = 0; mt < 4; mt++) {
        #pragma unroll
        for (int nt = 0; nt < 4; nt++) {
            const int r = row0 + wr * 64 + mt * 16 + (lane >> 2);
            const int ccol = col0 + wc * 32 + nt * 8 + ((lane & 3) << 1);
            const float b0 = bias[ccol], b1 = bias[ccol + 1];
            #pragma unroll
            for (int hh = 0; hh < 2; hh++) {
                const int rr = r + hh * 8;
                float v0 = c[mt][nt][hh * 2 + 0] + b0;
                float v1 = c[mt][nt][hh * 2 + 1] + b1;
                if (mode == 1 || mode == 3) {
                    if (mode == 1) { v0 = gelu_exact(v0); v1 = gelu_exact(v1); }
                    uint32_t wh, wl;
                    split_pack2(v0, v1, wh, wl);
                    *(uint32_t*)(ohi + (size_t)rr * N + ccol) = wh;
                    *(uint32_t*)(olo + (size_t)rr * N + ccol) = wl;
                } else {
                    if (mode == 2) {
                        float2 rv = *(const float2*)(res + (size_t)rr * N + ccol);
                        v0 += rv.x; v1 += rv.y;
                    }
                    *(float2*)(outf + (size_t)rr * N + ccol) = make_float2(v0, v1);
                }
            }
        }
    }
}

// ================= HMMA fp16x2 Flash Attention =================
// Q kept full (hi/lo), K and V rounded to fp16 (hi only). P split hi/lo from fp32.
// SMEM (ushort idx): Qhi[128*72], Qlo[128*72], 2 stages of {Khi,Vhi}[64*72].
#define ASTR 72
#define AQ_H 0
#define AQ_L (128 * ASTR)
#define KV_BASE (2 * 128 * ASTR)
#define KV_STAGE (2 * 64 * ASTR)
#define KV_MAT (64 * ASTR)
#define ATT2_SMEM ((KV_BASE + 2 * KV_STAGE) * 2)   // 73728 bytes

__global__ __launch_bounds__(256, 2) void attn_mma(
    const unsigned short* __restrict__ qh, const unsigned short* __restrict__ ql,
    unsigned short* __restrict__ ohi, unsigned short* __restrict__ olo)
{
    extern __shared__ unsigned short asmem[];
    const uint32_t sB = smem_u32(asmem);
    const int tid = threadIdx.x;
    const int wid = tid >> 5, lane = tid & 31;
    const int bh = blockIdx.y;
    const int b = bh >> 4, h = bh & 15;
    const int q0 = blockIdx.x * 128;

    // ---- Q tile (128x64 hi/lo) ----
    {
        const int row = tid >> 2;
        const int jj = tid & 3;
        #pragma unroll
        for (int i = 0; i < 2; i++) {
            const size_t src = (size_t)(b * 2048 + q0 + row + i * 64) * D_QKV + h * D_HEAD + jj * 16;
            const int dst = (row + i * 64) * ASTR + jj * 16;
            *(uint4*)(asmem + AQ_H + dst)     = *(const uint4*)(qh + src);
            *(uint4*)(asmem + AQ_H + dst + 8) = *(const uint4*)(qh + src + 8);
            *(uint4*)(asmem + AQ_L + dst)     = *(const uint4*)(ql + src);
            *(uint4*)(asmem + AQ_L + dst + 8) = *(const uint4*)(ql + src + 8);
        }
    }

    auto issueKV = [&](int kt, int s) {
        const int row = tid >> 2;
        const int jj = tid & 3;
        const uint32_t dst = sB + (uint32_t)(KV_BASE + s * KV_STAGE + row * ASTR + jj * 16) * 2;
        const size_t srow = (size_t)(b * 2048 + kt + row) * D_QKV + h * D_HEAD + jj * 16;
        const unsigned short* khp = qh + srow + D_MODEL;
        const unsigned short* vhp = qh + srow + 2 * D_MODEL;
        cp16(dst,                  khp);  cp16(dst + 16,                  khp + 8);
        cp16(dst + KV_MAT * 2,     vhp);  cp16(dst + KV_MAT * 2 + 16,     vhp + 8);
    };

    float cO[8][4];
    #pragma unroll
    for (int nt = 0; nt < 8; nt++)
        #pragma unroll
        for (int i = 0; i < 4; i++) cO[nt][i] = 0.f;
    float m2[2] = {-1e30f, -1e30f};
    float l2[2] = {0.f, 0.f};

    const uint32_t qhB = sB + AQ_H * 2, qlB = sB + AQ_L * 2;

    issueKV(0, 0);
    CP_COMMIT();

    for (int it = 0; it < 32; it++) {
        const int s = it & 1;
        if (it + 1 < 32) { issueKV((it + 1) * 64, s ^ 1); CP_COMMIT(); CP_WAIT1(); }
        else             { CP_WAIT0(); }
        __syncthreads();

        const uint32_t khB = sB + (uint32_t)(KV_BASE + s * KV_STAGE) * 2;
        const uint32_t vhB = khB + KV_MAT * 2;

        // ---- S = Q K^T ----
        float cS[8][4];
        #pragma unroll
        for (int nt = 0; nt < 8; nt++)
            #pragma unroll
            for (int i = 0; i < 4; i++) cS[nt][i] = 0.f;

        const uint32_t arow = (uint32_t)(wid * 16 + (lane & 15)) * (ASTR * 2);
        const int g = lane >> 3;
        const int rn = (g >= 2) ? 8 : 0;
        #pragma unroll
        for (int kk = 0; kk < 4; kk++) {
            const uint32_t acol = (uint32_t)((kk * 16 + ((lane >> 4) << 3)) << 1);
            uint32_t ah[4], al[4];
            LDSM_X4(ah[0], ah[1], ah[2], ah[3], qhB + arow + acol);
            LDSM_X4(al[0], al[1], al[2], al[3], qlB + arow + acol);
            const uint32_t bcol = (uint32_t)((kk * 16 + ((g & 1) << 3)) << 1);
            #pragma unroll
            for (int nt2 = 0; nt2 < 4; nt2++) {
                const uint32_t brow = (uint32_t)(nt2 * 16 + rn + (lane & 7)) * (ASTR * 2);
                uint32_t bhf[4];
                LDSM_X4(bhf[0], bhf[1], bhf[2], bhf[3], khB + brow + bcol);
                MMA16816(cS[nt2*2],   ah, bhf);
                MMA16816(cS[nt2*2+1], ah, bhf + 2);
                MMA16816(cS[nt2*2],   al, bhf);
                MMA16816(cS[nt2*2+1], al, bhf + 2);
            }
        }
        #pragma unroll
        for (int nt = 0; nt < 8; nt++)
            #pragma unroll
            for (int i = 0; i < 4; i++) cS[nt][i] *= 0.125f;

        // ---- online softmax ----
        #pragma unroll
        for (int hh = 0; hh < 2; hh++) {
            float mx = cS[0][hh*2];
            #pragma unroll
            for (int nt = 0; nt < 8; nt++) {
                mx = fmaxf(mx, cS[nt][hh*2]);
                mx = fmaxf(mx, cS[nt][hh*2+1]);
            }
            mx = fmaxf(mx, __shfl_xor_sync(0xffffffffu, mx, 1));
            mx = fmaxf(mx, __shfl_xor_sync(0xffffffffu, mx, 2));
            const float mnew = fmaxf(m2[hh], mx);
            const float corr = __expf(m2[hh] - mnew);
            m2[hh] = mnew;
            float sum = 0.f;
            #pragma unroll
            for (int nt = 0; nt < 8; nt++) {
                float p0 = __expf(cS[nt][hh*2]   - mnew);
                float p1 = __expf(cS[nt][hh*2+1] - mnew);
                cS[nt][hh*2] = p0; cS[nt][hh*2+1] = p1;
                sum += p0 + p1;
            }
            sum += __shfl_xor_sync(0xffffffffu, sum, 1);
            sum += __shfl_xor_sync(0xffffffffu, sum, 2);
            l2[hh] = l2[hh] * corr + sum;
            #pragma unroll
            for (int nt = 0; nt < 8; nt++) {
                cO[nt][hh*2]   *= corr;
                cO[nt][hh*2+1] *= corr;
            }
        }

        // ---- O += P V ----
        const int tt = lane >> 3;
        const uint32_t vrow0 = (uint32_t)(((tt & 1) << 3) + (lane & 7)) * (ASTR * 2);
        const uint32_t vcoff = (uint32_t)((tt >> 1) << 3) * 2;
        #pragma unroll
        for (int kk2 = 0; kk2 < 4; kk2++) {
            uint32_t ahi[4], alo[4];
            split_pack2(cS[2*kk2][0],   cS[2*kk2][1],   ahi[0], alo[0]);
            split_pack2(cS[2*kk2][2],   cS[2*kk2][3],   ahi[1], alo[1]);
            split_pack2(cS[2*kk2+1][0], cS[2*kk2+1][1], ahi[2], alo[2]);
            split_pack2(cS[2*kk2+1][2], cS[2*kk2+1][3], ahi[3], alo[3]);
            const uint32_t vrow = vrow0 + (uint32_t)(kk2 * 16) * (ASTR * 2);
            #pragma unroll
            for (int nt2 = 0; nt2 < 4; nt2++) {
                const uint32_t vcol = (uint32_t)(nt2 * 16) * 2 + vcoff;
                uint32_t bvh[4];
                LDSM_X4_T(bvh[0], bvh[1], bvh[2], bvh[3], vhB + vrow + vcol);
                MMA16816(cO[nt2*2],   ahi, bvh);
                MMA16816(cO[nt2*2+1], ahi, bvh + 2);
                MMA16816(cO[nt2*2],   alo, bvh);
                MMA16816(cO[nt2*2+1], alo, bvh + 2);
            }
        }
        __syncthreads();
    }

    // ---- epilogue ----
    #pragma unroll
    for (int hh = 0; hh < 2; hh++) {
        const float inv = 1.0f / l2[hh];
        const int row = q0 + wid * 16 + (lane >> 2) + hh * 8;
        const size_t rbase = ((size_t)b * 2048 + row) * D_MODEL + h * D_HEAD + ((lane & 3) << 1);
        #pragma unroll
        for (int nt = 0; nt < 8; nt++) {
            float v0 = cO[nt][hh*2]   * inv;
            float v1 = cO[nt][hh*2+1] * inv;
            uint32_t wh, wl;
            split_pack2(v0, v1, wh, wl);
            *(uint32_t*)(ohi + rbase + nt * 8) = wh;
            *(uint32_t*)(olo + rbase + nt * 8) = wl;
        }
    }
}

// ================= launch =================
extern "C" void kernel_launch(void* const* d_in, const int* in_sizes, int n_in,
                              void* d_out, int out_size)
{
    (void)in_sizes; (void)n_in; (void)out_size;
    const float* x     = (const float*)d_in[0];
    const float* ln1_g = (const float*)d_in[1];
    const float* ln1_b = (const float*)d_in[2];
    const float* w_qkv = (const float*)d_in[3];
    const float* b_qkv = (const float*)d_in[4];
    const float* w_out = (const float*)d_in[5];
    const float* b_out = (const float*)d_in[6];
    const float* ln2_g = (const float*)d_in[7];
    const float* ln2_b = (const float*)d_in[8];
    const float* w1    = (const float*)d_in[9];
    const float* b1    = (const float*)d_in[10];
    const float* w2    = (const float*)d_in[11];
    const float* b2    = (const float*)d_in[12];
    float* out = (float*)d_out;

    float *x2;
    unsigned short *qvh, *qvl, *lnh, *lnl, *ath, *atl, *h1h, *h1l;
    unsigned short *wqh, *woh, *w1h, *w2h;
    cudaGetSymbolAddress((void**)&x2,  g_x2);
    cudaGetSymbolAddress((void**)&qvh, g_qkv_hi); cudaGetSymbolAddress((void**)&qvl, g_qkv_lo);
    cudaGetSymbolAddress((void**)&lnh, g_ln_hi); cudaGetSymbolAddress((void**)&lnl, g_ln_lo);
    cudaGetSymbolAddress((void**)&ath, g_at_hi); cudaGetSymbolAddress((void**)&atl, g_at_lo);
    cudaGetSymbolAddress((void**)&h1h, g_h1_hi); cudaGetSymbolAddress((void**)&h1l, g_h1_lo);
    cudaGetSymbolAddress((void**)&wqh, g_wqkv_h);
    cudaGetSymbolAddress((void**)&woh, g_wout_h);
    cudaGetSymbolAddress((void**)&w1h, g_w1_h);
    cudaGetSymbolAddress((void**)&w2h, g_w2_h);

    cudaFuncSetAttribute(attn_mma, cudaFuncAttributeMaxDynamicSharedMemorySize, ATT2_SMEM);
    cudaFuncSetAttribute(gemm_tc,  cudaFuncAttributeMaxDynamicSharedMemorySize, GT_SMEM);

    dim3 wb(32, 8);
    wconv_kernel<<<dim3(D_QKV / 32, D_MODEL / 32), wb>>>(w_qkv, wqh, D_MODEL, D_QKV);
    wconv_kernel<<<dim3(D_MODEL / 32, D_MODEL / 32), wb>>>(w_out, woh, D_MODEL, D_MODEL);
    wconv_kernel<<<dim3(D_FF / 32, D_MODEL / 32), wb>>>(w1, w1h, D_MODEL, D_FF);
    wconv_kernel<<<dim3(D_MODEL / 32, D_FF / 32), wb>>>(w2, w2h, D_FF, D_MODEL);

    ln_kernel<<<M_ROWS, 256>>>(x, ln1_g, ln1_b, lnh, lnl);
    gemm_tc<<<dim3(D_QKV / 128, M_ROWS / 128), 256, GT_SMEM>>>(
        lnh, lnl, wqh, b_qkv, nullptr, nullptr, qvh, qvl,
        M_ROWS, D_QKV, D_MODEL, 3);
    attn_mma<<<dim3(2048 / 128, 2 * N_HEADS), 256, ATT2_SMEM>>>(qvh, qvl, ath, atl);
    gemm_tc<<<dim3(D_MODEL / 128, M_ROWS / 128), 256, GT_SMEM>>>(
        ath, atl, woh, b_out, x, x2, nullptr, nullptr,
        M_ROWS, D_MODEL, D_MODEL, 2);
    ln_kernel<<<M_ROWS, 256>>>(x2, ln2_g, ln2_b, lnh, lnl);
    gemm_tc<<<dim3(D_FF / 128, M_ROWS / 128), 256, GT_SMEM>>>(
        lnh, lnl, w1h, b1, nullptr, nullptr, h1h, h1l,
        M_ROWS, D_FF, D_MODEL, 1);
    gemm_tc<<<dim3(D_MODEL / 128, M_ROWS / 128), 256, GT_SMEM>>>(
        h1h, h1l, w2h, b2, x2, out, nullptr, nullptr,
        M_ROWS, D_MODEL, D_FF, 2);
}

// round 11
// speedup vs baseline: 6.0362x; 1.5738x over previous
#include <cuda_runtime.h>
#include <cuda_fp16.h>
#include <math.h>
#include <stdint.h>

// Problem: B=2, S=2048, D=1024, H=16, DH=64
#define M_ROWS 4096
#define D_MODEL 1024
#define D_QKV   3072
#define D_FF    4096
#define N_HEADS 16
#define D_HEAD  64

// ---------------- scratch (device globals; no allocation) ----------------
__device__ float g_x2 [M_ROWS * D_MODEL];
__device__ unsigned short g_qkv_h[M_ROWS * D_QKV];
__device__ unsigned short g_ln_h [M_ROWS * D_MODEL];
__device__ unsigned short g_at_h [M_ROWS * D_MODEL];
__device__ unsigned short g_h1_h [M_ROWS * D_FF];
// transposed weights [N,K] fp16
__device__ unsigned short g_wqkv_h[D_QKV * D_MODEL];
__device__ unsigned short g_wout_h[D_MODEL * D_MODEL];
__device__ unsigned short g_w1_h[D_FF * D_MODEL];
__device__ unsigned short g_w2_h[D_MODEL * D_FF];

// ---------------- helpers ----------------
__device__ __forceinline__ uint32_t smem_u32(const void* p) {
    uint32_t a;
    asm("{ .reg .u64 t; cvta.to.shared.u64 t, %1; cvt.u32.u64 %0, t; }" : "=r"(a) : "l"(p));
    return a;
}
__device__ __forceinline__ void cp16(uint32_t dst, const void* src) {
    asm volatile("cp.async.cg.shared.global [%0], [%1], 16;" :: "r"(dst), "l"(src));
}
#define CP_COMMIT() asm volatile("cp.async.commit_group;" ::: "memory")
#define CP_WAIT1()  asm volatile("cp.async.wait_group 1;" ::: "memory")
#define CP_WAIT0()  asm volatile("cp.async.wait_group 0;" ::: "memory")

#define LDSM_X4(r0, r1, r2, r3, addr) \
    asm volatile("ldmatrix.sync.aligned.m8n8.x4.shared.b16 {%0,%1,%2,%3}, [%4];" \
        : "=r"(r0), "=r"(r1), "=r"(r2), "=r"(r3) : "r"(addr))

#define LDSM_X4_T(r0, r1, r2, r3, addr) \
    asm volatile("ldmatrix.sync.aligned.m8n8.x4.trans.shared.b16 {%0,%1,%2,%3}, [%4];" \
        : "=r"(r0), "=r"(r1), "=r"(r2), "=r"(r3) : "r"(addr))

#define MMA16816(c, a, b) \
    asm volatile("mma.sync.aligned.m16n8k16.row.col.f32.f16.f16.f32 " \
        "{%0,%1,%2,%3}, {%4,%5,%6,%7}, {%8,%9}, {%0,%1,%2,%3};" \
        : "+f"((c)[0]), "+f"((c)[1]), "+f"((c)[2]), "+f"((c)[3]) \
        : "r"((a)[0]), "r"((a)[1]), "r"((a)[2]), "r"((a)[3]), "r"((b)[0]), "r"((b)[1]))

__device__ __forceinline__ float gelu_exact(float v) {
    return 0.5f * v * (1.0f + erff(v * 0.70710678118654752f));
}
__device__ __forceinline__ uint32_t packh2(float x, float y) {
    uint32_t r;
    asm("{ .reg .b16 lo, hi; cvt.rn.f16.f32 lo, %1; cvt.rn.f16.f32 hi, %2; mov.b32 %0, {lo, hi}; }"
        : "=r"(r) : "f"(x), "f"(y));
    return r;
}

// ================= weight transpose + fp16 round =================
__global__ void wconv_kernel(const float* __restrict__ W,
                             unsigned short* __restrict__ Th, int K, int N)
{
    __shared__ float t[32][33];
    int n0 = blockIdx.x * 32, k0 = blockIdx.y * 32;
    int tx = threadIdx.x, ty = threadIdx.y;
    #pragma unroll
    for (int i = 0; i < 32; i += 8)
        t[ty + i][tx] = W[(size_t)(k0 + ty + i) * N + n0 + tx];
    __syncthreads();
    #pragma unroll
    for (int i = 0; i < 32; i += 8) {
        float v = t[tx][ty + i];
        Th[(size_t)(n0 + ty + i) * K + k0 + tx] =
            __half_as_ushort(__float2half_rn(v));
    }
}

// ================= LayerNorm (writes fp16) =================
__global__ __launch_bounds__(256) void ln_kernel(
    const float* __restrict__ x, const float* __restrict__ g,
    const float* __restrict__ b, unsigned short* __restrict__ y)
{
    int row = blockIdx.x;
    const float* xr = x + (size_t)row * D_MODEL;
    int tid = threadIdx.x;
    float4 v = *(const float4*)(xr + tid * 4);
    float s = v.x + v.y + v.z + v.w;
    float q = v.x*v.x + v.y*v.y + v.z*v.z + v.w*v.w;
    #pragma unroll
    for (int off = 16; off > 0; off >>= 1) {
        s += __shfl_xor_sync(0xffffffffu, s, off);
        q += __shfl_xor_sync(0xffffffffu, q, off);
    }
    __shared__ float sh_s[8], sh_q[8];
    int w = tid >> 5, lane = tid & 31;
    if (lane == 0) { sh_s[w] = s; sh_q[w] = q; }
    __syncthreads();
    if (tid == 0) {
        float ts = 0.f, tq = 0.f;
        #pragma unroll
        for (int i = 0; i < 8; i++) { ts += sh_s[i]; tq += sh_q[i]; }
        sh_s[0] = ts; sh_q[0] = tq;
    }
    __syncthreads();
    float mean = sh_s[0] * (1.f / D_MODEL);
    float var  = sh_q[0] * (1.f / D_MODEL) - mean * mean;
    float rstd = rsqrtf(var + 1e-5f);
    float4 gv = *(const float4*)(g + tid * 4);
    float4 bv = *(const float4*)(b + tid * 4);
    float o0 = (v.x - mean) * rstd * gv.x + bv.x;
    float o1 = (v.y - mean) * rstd * gv.y + bv.y;
    float o2 = (v.z - mean) * rstd * gv.z + bv.z;
    float o3 = (v.w - mean) * rstd * gv.w + bv.w;
    size_t off = (size_t)row * D_MODEL + tid * 4;
    *(uint2*)(y + off) = make_uint2(packh2(o0, o1), packh2(o2, o3));
}

// ================= HMMA fp16 GEMM =================
// C = A @ W^T (A fp16 [M,K], W fp16 [N,K]).
// mode 0: outf=C+bias ; 1: oh=h(gelu(C+bias)) ; 2: outf=C+bias+res ; 3: oh=h(C+bias)
// SMEM per stage: A, B — 2 x (128 rows x 80 B) = 20480 B. Double buffered.
#define GSTAGE 20480
#define GT_SMEM (2 * GSTAGE)

__global__ __launch_bounds__(256, 2) void gemm_tc(
    const unsigned short* __restrict__ A, const unsigned short* __restrict__ Bh,
    const float* __restrict__ bias, const float* __restrict__ res,
    float* __restrict__ outf, unsigned short* __restrict__ oh,
    int M, int N, int K, int mode)
{
    extern __shared__ char smem[];
    const uint32_t sb = smem_u32(smem);
    const int tid = threadIdx.x;
    const int wid = tid >> 5, lane = tid & 31;
    const int wr = wid >> 2, wc = wid & 3;
    const int row0 = blockIdx.y * 128, col0 = blockIdx.x * 128;

    const int lr = tid >> 2;
    const int lj = tid & 3;

    float c[4][4][4];
    #pragma unroll
    for (int mt = 0; mt < 4; mt++)
        #pragma unroll
        for (int nt = 0; nt < 4; nt++)
            #pragma unroll
            for (int i = 0; i < 4; i++) c[mt][nt][i] = 0.f;

    const int nch = K >> 5;

    auto issue = [&](int cc, int s) {
        const int k0 = cc * 32;
        const uint32_t base = sb + (uint32_t)s * GSTAGE;
        const uint32_t ro = (uint32_t)lr * 80u + (uint32_t)lj * 16u;
        const size_t asrc = (size_t)(row0 + lr) * K + k0 + lj * 8;
        const size_t bsrc = (size_t)(col0 + lr) * K + k0 + lj * 8;
        const size_t step = (size_t)64 * K;
        cp16(base +          ro,            A + asrc);
        cp16(base +          ro + 64 * 80u, A + asrc + step);
        cp16(base + 10240u + ro,            Bh + bsrc);
        cp16(base + 10240u + ro + 64 * 80u, Bh + bsrc + step);
    };

    issue(0, 0);
    CP_COMMIT();

    for (int cc = 0; cc < nch; cc++) {
        const int s = cc & 1;
        if (cc + 1 < nch) { issue(cc + 1, s ^ 1); CP_COMMIT(); CP_WAIT1(); }
        else              { CP_WAIT0(); }
        __syncthreads();

        const uint32_t aB = sb + (uint32_t)s * GSTAGE;
        const uint32_t bB = aB + 10240u;

        #pragma unroll
        for (int kk = 0; kk < 32; kk += 16) {
            uint32_t a[4][4], bh[4][2];
            const uint32_t acol = (uint32_t)((kk + ((lane >> 4) << 3)) << 1);
            const uint32_t arow = (uint32_t)(wr * 64 + (lane & 15)) * 80u;
            #pragma unroll
            for (int mt = 0; mt < 4; mt++)
                LDSM_X4(a[mt][0], a[mt][1], a[mt][2], a[mt][3],
                        aB + arow + (uint32_t)(mt * 16) * 80u + acol);
            {
                const int g = lane >> 3;
                const int rn = (g >= 2) ? 8 : 0;
                const uint32_t bcol = (uint32_t)((kk + ((g & 1) << 3)) << 1);
                const uint32_t brow = (uint32_t)(wc * 32 + rn + (lane & 7)) * 80u;
                #pragma unroll
                for (int nt2 = 0; nt2 < 2; nt2++)
                    LDSM_X4(bh[nt2*2][0], bh[nt2*2][1], bh[nt2*2+1][0], bh[nt2*2+1][1],
                            bB + brow + (uint32_t)(nt2 * 16) * 80u + bcol);
            }
            #pragma unroll
            for (int mt = 0; mt < 4; mt++)
                #pragma unroll
                for (int nt = 0; nt < 4; nt++)
                    MMA16816(c[mt][nt], a[mt], bh[nt]);
        }
        __syncthreads();
    }

    #pragma unroll
    for (int mt = 0; mt < 4; mt++) {
        #pragma unroll
        for (int nt = 0; nt < 4; nt++) {
            const int r = row0 + wr * 64 + mt * 16 + (lane >> 2);
            const int ccol = col0 + wc * 32 + nt * 8 + ((lane & 3) << 1);
            const float b0 = bias[ccol], b1 = bias[ccol + 1];
            #pragma unroll
            for (int hh = 0; hh < 2; hh++) {
                const int rr = r + hh * 8;
                float v0 = c[mt][nt][hh * 2 + 0] + b0;
                float v1 = c[mt][nt][hh * 2 + 1] + b1;
                if (mode == 1 || mode == 3) {
                    if (mode == 1) { v0 = gelu_exact(v0); v1 = gelu_exact(v1); }
                    *(uint32_t*)(oh + (size_t)rr * N + ccol) = packh2(v0, v1);
                } else {
                    if (mode == 2) {
                        float2 rv = *(const float2*)(res + (size_t)rr * N + ccol);
                        v0 += rv.x; v1 += rv.y;
                    }
                    *(float2*)(outf + (size_t)rr * N + ccol) = make_float2(v0, v1);
                }
            }
        }
    }
}

// ================= HMMA fp16 Flash Attention =================
// SMEM (ushort idx): Q[128*72], 2 stages of {K,V}[64*72]. 55296 bytes.
#define ASTR 72
#define AQ 0
#define KV_BASE (128 * ASTR)
#define KV_STAGE (2 * 64 * ASTR)
#define KV_MAT (64 * ASTR)
#define ATT2_SMEM ((KV_BASE + 2 * KV_STAGE) * 2)

__global__ __launch_bounds__(256, 2) void attn_mma(
    const unsigned short* __restrict__ qkv, unsigned short* __restrict__ oh)
{
    extern __shared__ unsigned short asmem[];
    const uint32_t sB = smem_u32(asmem);
    const int tid = threadIdx.x;
    const int wid = tid >> 5, lane = tid & 31;
    const int bh = blockIdx.y;
    const int b = bh >> 4, h = bh & 15;
    const int q0 = blockIdx.x * 128;

    // ---- Q tile (128x64 fp16) ----
    {
        const int row = tid >> 2;
        const int jj = tid & 3;
        #pragma unroll
        for (int i = 0; i < 2; i++) {
            const size_t src = (size_t)(b * 2048 + q0 + row + i * 64) * D_QKV + h * D_HEAD + jj * 16;
            const int dst = (row + i * 64) * ASTR + jj * 16;
            *(uint4*)(asmem + AQ + dst)     = *(const uint4*)(qkv + src);
            *(uint4*)(asmem + AQ + dst + 8) = *(const uint4*)(qkv + src + 8);
        }
    }

    auto issueKV = [&](int kt, int s) {
        const int row = tid >> 2;
        const int jj = tid & 3;
        const uint32_t dst = sB + (uint32_t)(KV_BASE + s * KV_STAGE + row * ASTR + jj * 16) * 2;
        const size_t srow = (size_t)(b * 2048 + kt + row) * D_QKV + h * D_HEAD + jj * 16;
        const unsigned short* kp = qkv + srow + D_MODEL;
        const unsigned short* vp = qkv + srow + 2 * D_MODEL;
        cp16(dst,              kp);  cp16(dst + 16,              kp + 8);
        cp16(dst + KV_MAT * 2, vp);  cp16(dst + KV_MAT * 2 + 16, vp + 8);
    };

    float cO[8][4];
    #pragma unroll
    for (int nt = 0; nt < 8; nt++)
        #pragma unroll
        for (int i = 0; i < 4; i++) cO[nt][i] = 0.f;
    float m2[2] = {-1e30f, -1e30f};
    float l2[2] = {0.f, 0.f};

    const uint32_t qB = sB + AQ * 2;

    issueKV(0, 0);
    CP_COMMIT();

    for (int it = 0; it < 32; it++) {
        const int s = it & 1;
        if (it + 1 < 32) { issueKV((it + 1) * 64, s ^ 1); CP_COMMIT(); CP_WAIT1(); }
        else             { CP_WAIT0(); }
        __syncthreads();

        const uint32_t kB = sB + (uint32_t)(KV_BASE + s * KV_STAGE) * 2;
        const uint32_t vB = kB + KV_MAT * 2;

        // ---- S = Q K^T ----
        float cS[8][4];
        #pragma unroll
        for (int nt = 0; nt < 8; nt++)
            #pragma unroll
            for (int i = 0; i < 4; i++) cS[nt][i] = 0.f;

        const uint32_t arow = (uint32_t)(wid * 16 + (lane & 15)) * (ASTR * 2);
        const int g = lane >> 3;
        const int rn = (g >= 2) ? 8 : 0;
        #pragma unroll
        for (int kk = 0; kk < 4; kk++) {
            const uint32_t acol = (uint32_t)((kk * 16 + ((lane >> 4) << 3)) << 1);
            uint32_t a[4];
            LDSM_X4(a[0], a[1], a[2], a[3], qB + arow + acol);
            const uint32_t bcol = (uint32_t)((kk * 16 + ((g & 1) << 3)) << 1);
            #pragma unroll
            for (int nt2 = 0; nt2 < 4; nt2++) {
                const uint32_t brow = (uint32_t)(nt2 * 16 + rn + (lane & 7)) * (ASTR * 2);
                uint32_t bk[4];
                LDSM_X4(bk[0], bk[1], bk[2], bk[3], kB + brow + bcol);
                MMA16816(cS[nt2*2],   a, bk);
                MMA16816(cS[nt2*2+1], a, bk + 2);
            }
        }
        #pragma unroll
        for (int nt = 0; nt < 8; nt++)
            #pragma unroll
            for (int i = 0; i < 4; i++) cS[nt][i] *= 0.125f;

        // ---- online softmax ----
        #pragma unroll
        for (int hh = 0; hh < 2; hh++) {
            float mx = cS[0][hh*2];
            #pragma unroll
            for (int nt = 0; nt < 8; nt++) {
                mx = fmaxf(mx, cS[nt][hh*2]);
                mx = fmaxf(mx, cS[nt][hh*2+1]);
            }
            mx = fmaxf(mx, __shfl_xor_sync(0xffffffffu, mx, 1));
            mx = fmaxf(mx, __shfl_xor_sync(0xffffffffu, mx, 2));
            const float mnew = fmaxf(m2[hh], mx);
            const float corr = __expf(m2[hh] - mnew);
            m2[hh] = mnew;
            float sum = 0.f;
            #pragma unroll
            for (int nt = 0; nt < 8; nt++) {
                float p0 = __expf(cS[nt][hh*2]   - mnew);
                float p1 = __expf(cS[nt][hh*2+1] - mnew);
                cS[nt][hh*2] = p0; cS[nt][hh*2+1] = p1;
                sum += p0 + p1;
            }
            sum += __shfl_xor_sync(0xffffffffu, sum, 1);
            sum += __shfl_xor_sync(0xffffffffu, sum, 2);
            l2[hh] = l2[hh] * corr + sum;
            #pragma unroll
            for (int nt = 0; nt < 8; nt++) {
                cO[nt][hh*2]   *= corr;
                cO[nt][hh*2+1] *= corr;
            }
        }

        // ---- O += P V ----
        const int tt = lane >> 3;
        const uint32_t vrow0 = (uint32_t)(((tt & 1) << 3) + (lane & 7)) * (ASTR * 2);
        const uint32_t vcoff = (uint32_t)((tt >> 1) << 3) * 2;
        #pragma unroll
        for (int kk2 = 0; kk2 < 4; kk2++) {
            uint32_t ap[4];
            ap[0] = packh2(cS[2*kk2][0],   cS[2*kk2][1]);
            ap[1] = packh2(cS[2*kk2][2],   cS[2*kk2][3]);
            ap[2] = packh2(cS[2*kk2+1][0], cS[2*kk2+1][1]);
            ap[3] = packh2(cS[2*kk2+1][2], cS[2*kk2+1][3]);
            const uint32_t vrow = vrow0 + (uint32_t)(kk2 * 16) * (ASTR * 2);
            #pragma unroll
            for (int nt2 = 0; nt2 < 4; nt2++) {
                const uint32_t vcol = (uint32_t)(nt2 * 16) * 2 + vcoff;
                uint32_t bv[4];
                LDSM_X4_T(bv[0], bv[1], bv[2], bv[3], vB + vrow + vcol);
                MMA16816(cO[nt2*2],   ap, bv);
                MMA16816(cO[nt2*2+1], ap, bv + 2);
            }
        }
        __syncthreads();
    }

    // ---- epilogue ----
    #pragma unroll
    for (int hh = 0; hh < 2; hh++) {
        const float inv = 1.0f / l2[hh];
        const int row = q0 + wid * 16 + (lane >> 2) + hh * 8;
        const size_t rbase = ((size_t)b * 2048 + row) * D_MODEL + h * D_HEAD + ((lane & 3) << 1);
        #pragma unroll
        for (int nt = 0; nt < 8; nt++) {
            *(uint32_t*)(oh + rbase + nt * 8) =
                packh2(cO[nt][hh*2] * inv, cO[nt][hh*2+1] * inv);
        }
    }
}

// ================= launch =================
extern "C" void kernel_launch(void* const* d_in, const int* in_sizes, int n_in,
                              void* d_out, int out_size)
{
    (void)in_sizes; (void)n_in; (void)out_size;
    const float* x     = (const float*)d_in[0];
    const float* ln1_g = (const float*)d_in[1];
    const float* ln1_b = (const float*)d_in[2];
    const float* w_qkv = (const float*)d_in[3];
    const float* b_qkv = (const float*)d_in[4];
    const float* w_out = (const float*)d_in[5];
    const float* b_out = (const float*)d_in[6];
    const float* ln2_g = (const float*)d_in[7];
    const float* ln2_b = (const float*)d_in[8];
    const float* w1    = (const float*)d_in[9];
    const float* b1    = (const float*)d_in[10];
    const float* w2    = (const float*)d_in[11];
    const float* b2    = (const float*)d_in[12];
    float* out = (float*)d_out;

    float *x2;
    unsigned short *qvh, *lnh, *ath, *h1h, *wqh, *woh, *w1h, *w2h;
    cudaGetSymbolAddress((void**)&x2,  g_x2);
    cudaGetSymbolAddress((void**)&qvh, g_qkv_h);
    cudaGetSymbolAddress((void**)&lnh, g_ln_h);
    cudaGetSymbolAddress((void**)&ath, g_at_h);
    cudaGetSymbolAddress((void**)&h1h, g_h1_h);
    cudaGetSymbolAddress((void**)&wqh, g_wqkv_h);
    cudaGetSymbolAddress((void**)&woh, g_wout_h);
    cudaGetSymbolAddress((void**)&w1h, g_w1_h);
    cudaGetSymbolAddress((void**)&w2h, g_w2_h);

    cudaFuncSetAttribute(attn_mma, cudaFuncAttributeMaxDynamicSharedMemorySize, ATT2_SMEM);
    cudaFuncSetAttribute(gemm_tc,  cudaFuncAttributeMaxDynamicSharedMemorySize, GT_SMEM);

    dim3 wb(32, 8);
    wconv_kernel<<<dim3(D_QKV / 32, D_MODEL / 32), wb>>>(w_qkv, wqh, D_MODEL, D_QKV);
    wconv_kernel<<<dim3(D_MODEL / 32, D_MODEL / 32), wb>>>(w_out, woh, D_MODEL, D_MODEL);
    wconv_kernel<<<dim3(D_FF / 32, D_MODEL / 32), wb>>>(w1, w1h, D_MODEL, D_FF);
    wconv_kernel<<<dim3(D_MODEL / 32, D_FF / 32), wb>>>(w2, w2h, D_FF, D_MODEL);

    ln_kernel<<<M_ROWS, 256>>>(x, ln1_g, ln1_b, lnh);
    gemm_tc<<<dim3(D_QKV / 128, M_ROWS / 128), 256, GT_SMEM>>>(
        lnh, wqh, b_qkv, nullptr, nullptr, qvh, M_ROWS, D_QKV, D_MODEL, 3);
    attn_mma<<<dim3(2048 / 128, 2 * N_HEADS), 256, ATT2_SMEM>>>(qvh, ath);
    gemm_tc<<<dim3(D_MODEL / 128, M_ROWS / 128), 256, GT_SMEM>>>(
        ath, woh, b_out, x, x2, nullptr, M_ROWS, D_MODEL, D_MODEL, 2);
    ln_kernel<<<M_ROWS, 256>>>(x2, ln2_g, ln2_b, lnh);
    gemm_tc<<<dim3(D_FF / 128, M_ROWS / 128), 256, GT_SMEM>>>(
        lnh, w1h, b1, nullptr, nullptr, h1h, M_ROWS, D_FF, D_MODEL, 1);
    gemm_tc<<<dim3(D_MODEL / 128, M_ROWS / 128), 256, GT_SMEM>>>(
        h1h, w2h, b2, x2, out, nullptr, M_ROWS, D_MODEL, D_FF, 2);
}

// round 12
// speedup vs baseline: 6.3162x; 1.0464x over previous
#include <cuda_runtime.h>
#include <cuda_fp16.h>
#include <math.h>
#include <stdint.h>

// Problem: B=2, S=2048, D=1024, H=16, DH=64
#define M_ROWS 4096
#define D_MODEL 1024
#define D_QKV   3072
#define D_FF    4096
#define N_HEADS 16
#define D_HEAD  64

// ---------------- scratch (device globals; no allocation) ----------------
__device__ float g_x2 [M_ROWS * D_MODEL];
__device__ unsigned short g_qkv_h[M_ROWS * D_QKV];
__device__ unsigned short g_ln_h [M_ROWS * D_MODEL];
__device__ unsigned short g_at_h [M_ROWS * D_MODEL];
__device__ unsigned short g_h1_h [M_ROWS * D_FF];
// transposed weights [N,K] fp16
__device__ unsigned short g_wqkv_h[D_QKV * D_MODEL];
__device__ unsigned short g_wout_h[D_MODEL * D_MODEL];
__device__ unsigned short g_w1_h[D_FF * D_MODEL];
__device__ unsigned short g_w2_h[D_MODEL * D_FF];

// ---------------- helpers ----------------
__device__ __forceinline__ uint32_t smem_u32(const void* p) {
    uint32_t a;
    asm("{ .reg .u64 t; cvta.to.shared.u64 t, %1; cvt.u32.u64 %0, t; }" : "=r"(a) : "l"(p));
    return a;
}
__device__ __forceinline__ void cp16(uint32_t dst, const void* src) {
    asm volatile("cp.async.cg.shared.global [%0], [%1], 16;" :: "r"(dst), "l"(src));
}
#define CP_COMMIT() asm volatile("cp.async.commit_group;" ::: "memory")
#define CP_WAIT1()  asm volatile("cp.async.wait_group 1;" ::: "memory")
#define CP_WAIT0()  asm volatile("cp.async.wait_group 0;" ::: "memory")

#define LDSM_X4(r0, r1, r2, r3, addr) \
    asm volatile("ldmatrix.sync.aligned.m8n8.x4.shared.b16 {%0,%1,%2,%3}, [%4];" \
        : "=r"(r0), "=r"(r1), "=r"(r2), "=r"(r3) : "r"(addr))

#define LDSM_X4_T(r0, r1, r2, r3, addr) \
    asm volatile("ldmatrix.sync.aligned.m8n8.x4.trans.shared.b16 {%0,%1,%2,%3}, [%4];" \
        : "=r"(r0), "=r"(r1), "=r"(r2), "=r"(r3) : "r"(addr))

#define MMA16816(c, a, b) \
    asm volatile("mma.sync.aligned.m16n8k16.row.col.f32.f16.f16.f32 " \
        "{%0,%1,%2,%3}, {%4,%5,%6,%7}, {%8,%9}, {%0,%1,%2,%3};" \
        : "+f"((c)[0]), "+f"((c)[1]), "+f"((c)[2]), "+f"((c)[3]) \
        : "r"((a)[0]), "r"((a)[1]), "r"((a)[2]), "r"((a)[3]), "r"((b)[0]), "r"((b)[1]))

__device__ __forceinline__ float gelu_exact(float v) {
    return 0.5f * v * (1.0f + erff(v * 0.70710678118654752f));
}
__device__ __forceinline__ uint32_t packh2(float x, float y) {
    uint32_t r;
    asm("{ .reg .b16 lo, hi; cvt.rn.f16.f32 lo, %1; cvt.rn.f16.f32 hi, %2; mov.b32 %0, {lo, hi}; }"
        : "=r"(r) : "f"(x), "f"(y));
    return r;
}

// ================= weight transpose + fp16 round =================
__global__ void wconv_kernel(const float* __restrict__ W,
                             unsigned short* __restrict__ Th, int K, int N)
{
    __shared__ float t[32][33];
    int n0 = blockIdx.x * 32, k0 = blockIdx.y * 32;
    int tx = threadIdx.x, ty = threadIdx.y;
    #pragma unroll
    for (int i = 0; i < 32; i += 8)
        t[ty + i][tx] = W[(size_t)(k0 + ty + i) * N + n0 + tx];
    __syncthreads();
    #pragma unroll
    for (int i = 0; i < 32; i += 8) {
        float v = t[tx][ty + i];
        Th[(size_t)(n0 + ty + i) * K + k0 + tx] =
            __half_as_ushort(__float2half_rn(v));
    }
}

// ================= LayerNorm (writes fp16) =================
__global__ __launch_bounds__(256) void ln_kernel(
    const float* __restrict__ x, const float* __restrict__ g,
    const float* __restrict__ b, unsigned short* __restrict__ y)
{
    int row = blockIdx.x;
    const float* xr = x + (size_t)row * D_MODEL;
    int tid = threadIdx.x;
    float4 v = *(const float4*)(xr + tid * 4);
    float s = v.x + v.y + v.z + v.w;
    float q = v.x*v.x + v.y*v.y + v.z*v.z + v.w*v.w;
    #pragma unroll
    for (int off = 16; off > 0; off >>= 1) {
        s += __shfl_xor_sync(0xffffffffu, s, off);
        q += __shfl_xor_sync(0xffffffffu, q, off);
    }
    __shared__ float sh_s[8], sh_q[8];
    int w = tid >> 5, lane = tid & 31;
    if (lane == 0) { sh_s[w] = s; sh_q[w] = q; }
    __syncthreads();
    if (tid == 0) {
        float ts = 0.f, tq = 0.f;
        #pragma unroll
        for (int i = 0; i < 8; i++) { ts += sh_s[i]; tq += sh_q[i]; }
        sh_s[0] = ts; sh_q[0] = tq;
    }
    __syncthreads();
    float mean = sh_s[0] * (1.f / D_MODEL);
    float var  = sh_q[0] * (1.f / D_MODEL) - mean * mean;
    float rstd = rsqrtf(var + 1e-5f);
    float4 gv = *(const float4*)(g + tid * 4);
    float4 bv = *(const float4*)(b + tid * 4);
    float o0 = (v.x - mean) * rstd * gv.x + bv.x;
    float o1 = (v.y - mean) * rstd * gv.y + bv.y;
    float o2 = (v.z - mean) * rstd * gv.z + bv.z;
    float o3 = (v.w - mean) * rstd * gv.w + bv.w;
    size_t off = (size_t)row * D_MODEL + tid * 4;
    *(uint2*)(y + off) = make_uint2(packh2(o0, o1), packh2(o2, o3));
}

// ================= HMMA fp16 GEMM, BK=64 =================
// C = A @ W^T. mode 0: outf=C+bias ; 1: oh=h(gelu(C+bias)) ; 2: outf=C+bias+res ; 3: oh=h(C+bias)
// SMEM per stage: A,B — 2 x (128 rows x 144 B) = 36864 B. Double buffered.
#define GROW 144
#define GMAT (128 * GROW)
#define GSTAGE (2 * GMAT)
#define GT_SMEM (2 * GSTAGE)

__global__ __launch_bounds__(256, 2) void gemm_tc(
    const unsigned short* __restrict__ A, const unsigned short* __restrict__ Bh,
    const float* __restrict__ bias, const float* __restrict__ res,
    float* __restrict__ outf, unsigned short* __restrict__ oh,
    int M, int N, int K, int mode)
{
    extern __shared__ char smem[];
    const uint32_t sb = smem_u32(smem);
    const int tid = threadIdx.x;
    const int wid = tid >> 5, lane = tid & 31;
    const int wr = wid >> 2, wc = wid & 3;
    const int row0 = blockIdx.y * 128, col0 = blockIdx.x * 128;

    const int lr = tid >> 2;       // 0..63 (row, two halves)
    const int lj = tid & 3;        // chunk pair

    float c[4][4][4];
    #pragma unroll
    for (int mt = 0; mt < 4; mt++)
        #pragma unroll
        for (int nt = 0; nt < 4; nt++)
            #pragma unroll
            for (int i = 0; i < 4; i++) c[mt][nt][i] = 0.f;

    const int nch = K >> 6;

    auto issue = [&](int cc, int s) {
        const int k0 = cc * 64;
        const uint32_t base = sb + (uint32_t)s * GSTAGE;
        const uint32_t ro = (uint32_t)lr * GROW + (uint32_t)lj * 16u;
        const size_t asrc = (size_t)(row0 + lr) * K + k0 + lj * 8;
        const size_t bsrc = (size_t)(col0 + lr) * K + k0 + lj * 8;
        const size_t step = (size_t)64 * K;
        // A matrix: rows lr and lr+64; chunks lj and lj+4 (bytes +64 / elems +32)
        cp16(base + ro,                       A + asrc);
        cp16(base + ro + 64u,                 A + asrc + 32);
        cp16(base + ro + 64u * GROW,          A + asrc + step);
        cp16(base + ro + 64u * GROW + 64u,    A + asrc + step + 32);
        // B matrix
        const uint32_t bb = base + GMAT;
        cp16(bb + ro,                         Bh + bsrc);
        cp16(bb + ro + 64u,                   Bh + bsrc + 32);
        cp16(bb + ro + 64u * GROW,            Bh + bsrc + step);
        cp16(bb + ro + 64u * GROW + 64u,      Bh + bsrc + step + 32);
    };

    issue(0, 0);
    CP_COMMIT();

    for (int cc = 0; cc < nch; cc++) {
        const int s = cc & 1;
        if (cc + 1 < nch) { issue(cc + 1, s ^ 1); CP_COMMIT(); CP_WAIT1(); }
        else              { CP_WAIT0(); }
        __syncthreads();

        const uint32_t aB = sb + (uint32_t)s * GSTAGE;
        const uint32_t bB = aB + GMAT;

        #pragma unroll
        for (int kk = 0; kk < 64; kk += 16) {
            uint32_t a[4][4], bh[4][2];
            const uint32_t acol = (uint32_t)((kk + ((lane >> 4) << 3)) << 1);
            const uint32_t arow = (uint32_t)(wr * 64 + (lane & 15)) * GROW;
            #pragma unroll
            for (int mt = 0; mt < 4; mt++)
                LDSM_X4(a[mt][0], a[mt][1], a[mt][2], a[mt][3],
                        aB + arow + (uint32_t)(mt * 16) * GROW + acol);
            {
                const int g = lane >> 3;
                const int rn = (g >= 2) ? 8 : 0;
                const uint32_t bcol = (uint32_t)((kk + ((g & 1) << 3)) << 1);
                const uint32_t brow = (uint32_t)(wc * 32 + rn + (lane & 7)) * GROW;
                #pragma unroll
                for (int nt2 = 0; nt2 < 2; nt2++)
                    LDSM_X4(bh[nt2*2][0], bh[nt2*2][1], bh[nt2*2+1][0], bh[nt2*2+1][1],
                            bB + brow + (uint32_t)(nt2 * 16) * GROW + bcol);
            }
            #pragma unroll
            for (int mt = 0; mt < 4; mt++)
                #pragma unroll
                for (int nt = 0; nt < 4; nt++)
                    MMA16816(c[mt][nt], a[mt], bh[nt]);
        }
        __syncthreads();
    }

    #pragma unroll
    for (int mt = 0; mt < 4; mt++) {
        #pragma unroll
        for (int nt = 0; nt < 4; nt++) {
            const int r = row0 + wr * 64 + mt * 16 + (lane >> 2);
            const int ccol = col0 + wc * 32 + nt * 8 + ((lane & 3) << 1);
            const float b0 = bias[ccol], b1 = bias[ccol + 1];
            #pragma unroll
            for (int hh = 0; hh < 2; hh++) {
                const int rr = r + hh * 8;
                float v0 = c[mt][nt][hh * 2 + 0] + b0;
                float v1 = c[mt][nt][hh * 2 + 1] + b1;
                if (mode == 1 || mode == 3) {
                    if (mode == 1) { v0 = gelu_exact(v0); v1 = gelu_exact(v1); }
                    *(uint32_t*)(oh + (size_t)rr * N + ccol) = packh2(v0, v1);
                } else {
                    if (mode == 2) {
                        float2 rv = *(const float2*)(res + (size_t)rr * N + ccol);
                        v0 += rv.x; v1 += rv.y;
                    }
                    *(float2*)(outf + (size_t)rr * N + ccol) = make_float2(v0, v1);
                }
            }
        }
    }
}

// ================= HMMA fp16 Flash Attention =================
// log2-domain softmax; deferred l reduction (quad-reduce once at end).
// SMEM (ushort idx): Q[128*72], 2 stages of {K,V}[64*72]. 55296 bytes.
#define ASTR 72
#define AQ 0
#define KV_BASE (128 * ASTR)
#define KV_STAGE (2 * 64 * ASTR)
#define KV_MAT (64 * ASTR)
#define ATT2_SMEM ((KV_BASE + 2 * KV_STAGE) * 2)

__global__ __launch_bounds__(256, 2) void attn_mma(
    const unsigned short* __restrict__ qkv, unsigned short* __restrict__ oh)
{
    extern __shared__ unsigned short asmem[];
    const uint32_t sB = smem_u32(asmem);
    const int tid = threadIdx.x;
    const int wid = tid >> 5, lane = tid & 31;
    const int bh = blockIdx.y;
    const int b = bh >> 4, h = bh & 15;
    const int q0 = blockIdx.x * 128;

    // ---- Q tile (128x64 fp16) ----
    {
        const int row = tid >> 2;
        const int jj = tid & 3;
        #pragma unroll
        for (int i = 0; i < 2; i++) {
            const size_t src = (size_t)(b * 2048 + q0 + row + i * 64) * D_QKV + h * D_HEAD + jj * 16;
            const int dst = (row + i * 64) * ASTR + jj * 16;
            *(uint4*)(asmem + AQ + dst)     = *(const uint4*)(qkv + src);
            *(uint4*)(asmem + AQ + dst + 8) = *(const uint4*)(qkv + src + 8);
        }
    }

    auto issueKV = [&](int kt, int s) {
        const int row = tid >> 2;
        const int jj = tid & 3;
        const uint32_t dst = sB + (uint32_t)(KV_BASE + s * KV_STAGE + row * ASTR + jj * 16) * 2;
        const size_t srow = (size_t)(b * 2048 + kt + row) * D_QKV + h * D_HEAD + jj * 16;
        const unsigned short* kp = qkv + srow + D_MODEL;
        const unsigned short* vp = qkv + srow + 2 * D_MODEL;
        cp16(dst,              kp);  cp16(dst + 16,              kp + 8);
        cp16(dst + KV_MAT * 2, vp);  cp16(dst + KV_MAT * 2 + 16, vp + 8);
    };

    float cO[8][4];
    #pragma unroll
    for (int nt = 0; nt < 8; nt++)
        #pragma unroll
        for (int i = 0; i < 4; i++) cO[nt][i] = 0.f;
    float m2[2] = {-1e30f, -1e30f};
    float l2[2] = {0.f, 0.f};          // per-thread partial (quad-reduced at end)

    const uint32_t qB = sB + AQ * 2;
    const float c0 = 0.125f * 1.4426950408889634f;   // (1/sqrt(64)) * log2(e)

    issueKV(0, 0);
    CP_COMMIT();

    for (int it = 0; it < 32; it++) {
        const int s = it & 1;
        if (it + 1 < 32) { issueKV((it + 1) * 64, s ^ 1); CP_COMMIT(); CP_WAIT1(); }
        else             { CP_WAIT0(); }
        __syncthreads();

        const uint32_t kB = sB + (uint32_t)(KV_BASE + s * KV_STAGE) * 2;
        const uint32_t vB = kB + KV_MAT * 2;

        // ---- S = Q K^T ----
        float cS[8][4];
        #pragma unroll
        for (int nt = 0; nt < 8; nt++)
            #pragma unroll
            for (int i = 0; i < 4; i++) cS[nt][i] = 0.f;

        const uint32_t arow = (uint32_t)(wid * 16 + (lane & 15)) * (ASTR * 2);
        const int g = lane >> 3;
        const int rn = (g >= 2) ? 8 : 0;
        #pragma unroll
        for (int kk = 0; kk < 4; kk++) {
            const uint32_t acol = (uint32_t)((kk * 16 + ((lane >> 4) << 3)) << 1);
            uint32_t a[4];
            LDSM_X4(a[0], a[1], a[2], a[3], qB + arow + acol);
            const uint32_t bcol = (uint32_t)((kk * 16 + ((g & 1) << 3)) << 1);
            #pragma unroll
            for (int nt2 = 0; nt2 < 4; nt2++) {
                const uint32_t brow = (uint32_t)(nt2 * 16 + rn + (lane & 7)) * (ASTR * 2);
                uint32_t bk[4];
                LDSM_X4(bk[0], bk[1], bk[2], bk[3], kB + brow + bcol);
                MMA16816(cS[nt2*2],   a, bk);
                MMA16816(cS[nt2*2+1], a, bk + 2);
            }
        }
        // scale into log2 domain
        #pragma unroll
        for (int nt = 0; nt < 8; nt++)
            #pragma unroll
            for (int i = 0; i < 4; i++) cS[nt][i] *= c0;

        // ---- online softmax (log2 domain; deferred l reduction) ----
        #pragma unroll
        for (int hh = 0; hh < 2; hh++) {
            float mx = cS[0][hh*2];
            #pragma unroll
            for (int nt = 0; nt < 8; nt++) {
                mx = fmaxf(mx, cS[nt][hh*2]);
                mx = fmaxf(mx, cS[nt][hh*2+1]);
            }
            mx = fmaxf(mx, __shfl_xor_sync(0xffffffffu, mx, 1));
            mx = fmaxf(mx, __shfl_xor_sync(0xffffffffu, mx, 2));
            const float mnew = fmaxf(m2[hh], mx);
            const float corr = exp2f(m2[hh] - mnew);
            m2[hh] = mnew;
            float sum = 0.f;
            #pragma unroll
            for (int nt = 0; nt < 8; nt++) {
                float p0 = exp2f(cS[nt][hh*2]   - mnew);
                float p1 = exp2f(cS[nt][hh*2+1] - mnew);
                cS[nt][hh*2] = p0; cS[nt][hh*2+1] = p1;
                sum += p0 + p1;
            }
            l2[hh] = l2[hh] * corr + sum;
            #pragma unroll
            for (int nt = 0; nt < 8; nt++) {
                cO[nt][hh*2]   *= corr;
                cO[nt][hh*2+1] *= corr;
            }
        }

        // ---- O += P V ----
        const int tt = lane >> 3;
        const uint32_t vrow0 = (uint32_t)(((tt & 1) << 3) + (lane & 7)) * (ASTR * 2);
        const uint32_t vcoff = (uint32_t)((tt >> 1) << 3) * 2;
        #pragma unroll
        for (int kk2 = 0; kk2 < 4; kk2++) {
            uint32_t ap[4];
            ap[0] = packh2(cS[2*kk2][0],   cS[2*kk2][1]);
            ap[1] = packh2(cS[2*kk2][2],   cS[2*kk2][3]);
            ap[2] = packh2(cS[2*kk2+1][0], cS[2*kk2+1][1]);
            ap[3] = packh2(cS[2*kk2+1][2], cS[2*kk2+1][3]);
            const uint32_t vrow = vrow0 + (uint32_t)(kk2 * 16) * (ASTR * 2);
            #pragma unroll
            for (int nt2 = 0; nt2 < 4; nt2++) {
                const uint32_t vcol = (uint32_t)(nt2 * 16) * 2 + vcoff;
                uint32_t bv[4];
                LDSM_X4_T(bv[0], bv[1], bv[2], bv[3], vB + vrow + vcol);
                MMA16816(cO[nt2*2],   ap, bv);
                MMA16816(cO[nt2*2+1], ap, bv + 2);
            }
        }
        __syncthreads();
    }

    // ---- final l reduction across quad + epilogue ----
    #pragma unroll
    for (int hh = 0; hh < 2; hh++) {
        float lsum = l2[hh];
        lsum += __shfl_xor_sync(0xffffffffu, lsum, 1);
        lsum += __shfl_xor_sync(0xffffffffu, lsum, 2);
        const float inv = 1.0f / lsum;
        const int row = q0 + wid * 16 + (lane >> 2) + hh * 8;
        const size_t rbase = ((size_t)b * 2048 + row) * D_MODEL + h * D_HEAD + ((lane & 3) << 1);
        #pragma unroll
        for (int nt = 0; nt < 8; nt++) {
            *(uint32_t*)(oh + rbase + nt * 8) =
                packh2(cO[nt][hh*2] * inv, cO[nt][hh*2+1] * inv);
        }
    }
}

// ================= launch =================
extern "C" void kernel_launch(void* const* d_in, const int* in_sizes, int n_in,
                              void* d_out, int out_size)
{
    (void)in_sizes; (void)n_in; (void)out_size;
    const float* x     = (const float*)d_in[0];
    const float* ln1_g = (const float*)d_in[1];
    const float* ln1_b = (const float*)d_in[2];
    const float* w_qkv = (const float*)d_in[3];
    const float* b_qkv = (const float*)d_in[4];
    const float* w_out = (const float*)d_in[5];
    const float* b_out = (const float*)d_in[6];
    const float* ln2_g = (const float*)d_in[7];
    const float* ln2_b = (const float*)d_in[8];
    const float* w1    = (const float*)d_in[9];
    const float* b1    = (const float*)d_in[10];
    const float* w2    = (const float*)d_in[11];
    const float* b2    = (const float*)d_in[12];
    float* out = (float*)d_out;

    float *x2;
    unsigned short *qvh, *lnh, *ath, *h1h, *wqh, *woh, *w1h, *w2h;
    cudaGetSymbolAddress((void**)&x2,  g_x2);
    cudaGetSymbolAddress((void**)&qvh, g_qkv_h);
    cudaGetSymbolAddress((void**)&lnh, g_ln_h);
    cudaGetSymbolAddress((void**)&ath, g_at_h);
    cudaGetSymbolAddress((void**)&h1h, g_h1_h);
    cudaGetSymbolAddress((void**)&wqh, g_wqkv_h);
    cudaGetSymbolAddress((void**)&woh, g_wout_h);
    cudaGetSymbolAddress((void**)&w1h, g_w1_h);
    cudaGetSymbolAddress((void**)&w2h, g_w2_h);

    cudaFuncSetAttribute(attn_mma, cudaFuncAttributeMaxDynamicSharedMemorySize, ATT2_SMEM);
    cudaFuncSetAttribute(gemm_tc,  cudaFuncAttributeMaxDynamicSharedMemorySize, GT_SMEM);

    dim3 wb(32, 8);
    wconv_kernel<<<dim3(D_QKV / 32, D_MODEL / 32), wb>>>(w_qkv, wqh, D_MODEL, D_QKV);
    wconv_kernel<<<dim3(D_MODEL / 32, D_MODEL / 32), wb>>>(w_out, woh, D_MODEL, D_MODEL);
    wconv_kernel<<<dim3(D_FF / 32, D_MODEL / 32), wb>>>(w1, w1h, D_MODEL, D_FF);
    wconv_kernel<<<dim3(D_MODEL / 32, D_FF / 32), wb>>>(w2, w2h, D_FF, D_MODEL);

    ln_kernel<<<M_ROWS, 256>>>(x, ln1_g, ln1_b, lnh);
    gemm_tc<<<dim3(D_QKV / 128, M_ROWS / 128), 256, GT_SMEM>>>(
        lnh, wqh, b_qkv, nullptr, nullptr, qvh, M_ROWS, D_QKV, D_MODEL, 3);
    attn_mma<<<dim3(2048 / 128, 2 * N_HEADS), 256, ATT2_SMEM>>>(qvh, ath);
    gemm_tc<<<dim3(D_MODEL / 128, M_ROWS / 128), 256, GT_SMEM>>>(
        ath, woh, b_out, x, x2, nullptr, M_ROWS, D_MODEL, D_MODEL, 2);
    ln_kernel<<<M_ROWS, 256>>>(x2, ln2_g, ln2_b, lnh);
    gemm_tc<<<dim3(D_FF / 128, M_ROWS / 128), 256, GT_SMEM>>>(
        lnh, w1h, b1, nullptr, nullptr, h1h, M_ROWS, D_FF, D_MODEL, 1);
    gemm_tc<<<dim3(D_MODEL / 128, M_ROWS / 128), 256, GT_SMEM>>>(
        h1h, w2h, b2, x2, out, nullptr, M_ROWS, D_MODEL, D_FF, 2);
}